// round 8
// baseline (speedup 1.0000x reference)
#include <cuda_runtime.h>
#include <cstdint>

// Problem constants
#define BQ   64
#define NN   128
#define FIN  128
#define HH   512
#define MSGD 512
#define LL   4
#define ROWS (BQ*NN)      // 8192
#define TGT  12

// ---------------- scratch (device globals) ----------------
__device__ float g_h    [ROWS*HH];
__device__ float g_hproj[BQ*LL*NN*MSGD];
__device__ float g_m    [ROWS*MSGD];
__device__ float g_gi   [ROWS*3*HH];
__device__ float g_gh   [ROWS*3*HH];
__device__ float g_mask [ROWS];
__device__ float g_t0   [ROWS*256];
__device__ float g_t1   [ROWS*256];
__device__ float g_gate [ROWS*TGT];
__device__ float g_val  [ROWS*TGT];

// ---------------- tf32x3 tensor-core GEMM ----------------
__device__ __forceinline__ uint32_t f2tf(float x) {
    uint32_t r;
    asm("cvt.rna.tf32.f32 %0, %1;" : "=r"(r) : "f"(x));
    return r;
}
__device__ __forceinline__ void tfsplit(float x, uint32_t& hi, uint32_t& lo) {
    hi = f2tf(x);
    float hf = __uint_as_float(hi);
    lo = f2tf(x - hf);
}

__device__ __forceinline__ void mma_tf32(float* d, const uint32_t* a, const uint32_t* b) {
    asm volatile(
        "mma.sync.aligned.m16n8k8.row.col.f32.tf32.tf32.f32 "
        "{%0,%1,%2,%3}, {%4,%5,%6,%7}, {%8,%9}, {%0,%1,%2,%3};\n"
        : "+f"(d[0]), "+f"(d[1]), "+f"(d[2]), "+f"(d[3])
        : "r"(a[0]), "r"(a[1]), "r"(a[2]), "r"(a[3]), "r"(b[0]), "r"(b[1]));
}

__device__ __forceinline__ void ldsm_x4(uint32_t& r0, uint32_t& r1, uint32_t& r2, uint32_t& r3,
                                        uint32_t addr) {
    asm volatile("ldmatrix.sync.aligned.m8n8.x4.shared.b16 {%0,%1,%2,%3}, [%4];"
                 : "=r"(r0), "=r"(r1), "=r"(r2), "=r"(r3) : "r"(addr));
}

// Block tile 128x128, BK=16, 256 threads (8 warps = 4m x 2n), warp tile 32x64.
// Smem: A[m][k] (128x16, stride 20 words) hi+lo planes; B[n][k] (128x16, stride 20) hi+lo.
// Fragment loads via ldmatrix.x4; hi/lo STS vectorized as uint4.
// C[M,N] = A[M,K]*op(B) (+C if ACC) (+bias) then act.
// TRANSB: B row-major [N,K]; else [K,N]. Batched via blockIdx.z (zh=z/dv, zl=z%dv).
// Requires: M % 128 == 0, K % 16 == 0.
#define LDT 20   // smem row stride in words

template<bool TRANSB, bool ACC>
__global__ void __launch_bounds__(256)
tgemm_kernel(const float* __restrict__ A, int lda,
             const float* __restrict__ Bm, int ldb,
             float* __restrict__ C, int ldc,
             int M, int N, int K,
             const float* __restrict__ bias, int act,
             int dv,
             long long aHi, long long aLo,
             long long bHi, long long bLo,
             long long cHi, long long cLo)
{
    int z = blockIdx.z;
    int zh = z / dv, zl = z % dv;
    A  += zh*aHi + zl*aLo;
    Bm += zh*bHi + zl*bLo;
    C  += zh*cHi + zl*cLo;

    __shared__ uint32_t Ah[128 * LDT], Al[128 * LDT];
    __shared__ uint32_t Bh[128 * LDT], Bl[128 * LDT];

    int tid  = threadIdx.x;
    int lane = tid & 31;
    int wid  = tid >> 5;
    int gid  = lane >> 2;       // 0..7
    int tig  = lane & 3;        // 0..3
    int quad = lane >> 3;       // 0..3 (ldmatrix slab select)
    int rowin= lane & 7;        // row within slab
    int wm   = (wid & 3) * 32;  // warp m offset (4 warps in m)
    int wn   = (wid >> 2) * 64; // warp n offset (2 warps in n)
    int m0   = blockIdx.y * 128;
    int n0   = blockIdx.x * 128;

    uint32_t ah_b = (uint32_t)__cvta_generic_to_shared(Ah);
    uint32_t al_b = (uint32_t)__cvta_generic_to_shared(Al);
    uint32_t bh_b = (uint32_t)__cvta_generic_to_shared(Bh);
    uint32_t bl_b = (uint32_t)__cvta_generic_to_shared(Bl);

    // ldmatrix lane-address row offsets (in words), fixed per thread
    int rA0 = (wm + ((quad & 1) << 3) + rowin) * LDT + ((quad >> 1) << 2);
    int rA1 = rA0 + 16 * LDT;
    int rB0 = (wn + ((quad >> 1) << 3) + rowin) * LDT + ((quad & 1) << 2);
    int rB1 = rB0 + 16 * LDT;
    int rB2 = rB0 + 32 * LDT;
    int rB3 = rB0 + 48 * LDT;

    float4 aS[2], bS[2];
    const float4 f4z = make_float4(0.f, 0.f, 0.f, 0.f);

    auto ldg = [&](int k0) {
#pragma unroll
        for (int i = 0; i < 2; i++) {
            int f = i * 256 + tid;
            int r = f >> 2;
            int kq = (f & 3) * 4;
            aS[i] = *(const float4*)(A + (size_t)(m0 + r) * lda + k0 + kq);
            if (TRANSB) {
                int n = n0 + r;
                bS[i] = (n < N) ? *(const float4*)(Bm + (size_t)n * ldb + k0 + kq) : f4z;
            } else {
                int rr = f >> 5;           // 0..15 (k rows)
                int c = (f & 31) * 4;      // n col
                int n = n0 + c;
                bS[i] = (n < N) ? *(const float4*)(Bm + (size_t)(k0 + rr) * ldb + n) : f4z;
            }
        }
    };
    auto sts = [&]() {
#pragma unroll
        for (int i = 0; i < 2; i++) {
            int f = i * 256 + tid;
            int r = f >> 2;
            int kq = (f & 3) * 4;
            float av[4] = {aS[i].x, aS[i].y, aS[i].z, aS[i].w};
            uint32_t h4[4], l4[4];
#pragma unroll
            for (int q = 0; q < 4; q++) tfsplit(av[q], h4[q], l4[q]);
            *(uint4*)&Ah[r * LDT + kq] = make_uint4(h4[0], h4[1], h4[2], h4[3]);
            *(uint4*)&Al[r * LDT + kq] = make_uint4(l4[0], l4[1], l4[2], l4[3]);

            float bv[4] = {bS[i].x, bS[i].y, bS[i].z, bS[i].w};
            if (TRANSB) {
#pragma unroll
                for (int q = 0; q < 4; q++) tfsplit(bv[q], h4[q], l4[q]);
                *(uint4*)&Bh[r * LDT + kq] = make_uint4(h4[0], h4[1], h4[2], h4[3]);
                *(uint4*)&Bl[r * LDT + kq] = make_uint4(l4[0], l4[1], l4[2], l4[3]);
            } else {
                // transpose: global [k][n] -> smem [n][k]
                int rr = f >> 5;           // k
                int c = (f & 31) * 4;      // n
#pragma unroll
                for (int q = 0; q < 4; q++) {
                    uint32_t h, l;
                    tfsplit(bv[q], h, l);
                    Bh[(c + q) * LDT + rr] = h;
                    Bl[(c + q) * LDT + rr] = l;
                }
            }
        }
    };

    float acc[2][8][4];
#pragma unroll
    for (int mt = 0; mt < 2; mt++)
#pragma unroll
        for (int nt = 0; nt < 8; nt++)
#pragma unroll
            for (int q = 0; q < 4; q++) acc[mt][nt][q] = 0.f;

    ldg(0);
    sts();
    __syncthreads();

    for (int k0 = 0; k0 < K; k0 += 16) {
        int nxt = k0 + 16;
        if (nxt < K) ldg(nxt);   // prefetch into registers
#pragma unroll
        for (int kk = 0; kk < 16; kk += 8) {
            uint32_t afh[2][4], afl[2][4], bfh[8][2], bfl[8][2];
            ldsm_x4(afh[0][0], afh[0][1], afh[0][2], afh[0][3], ah_b + (rA0 + kk) * 4);
            ldsm_x4(afh[1][0], afh[1][1], afh[1][2], afh[1][3], ah_b + (rA1 + kk) * 4);
            ldsm_x4(afl[0][0], afl[0][1], afl[0][2], afl[0][3], al_b + (rA0 + kk) * 4);
            ldsm_x4(afl[1][0], afl[1][1], afl[1][2], afl[1][3], al_b + (rA1 + kk) * 4);
            ldsm_x4(bfh[0][0], bfh[0][1], bfh[1][0], bfh[1][1], bh_b + (rB0 + kk) * 4);
            ldsm_x4(bfh[2][0], bfh[2][1], bfh[3][0], bfh[3][1], bh_b + (rB1 + kk) * 4);
            ldsm_x4(bfh[4][0], bfh[4][1], bfh[5][0], bfh[5][1], bh_b + (rB2 + kk) * 4);
            ldsm_x4(bfh[6][0], bfh[6][1], bfh[7][0], bfh[7][1], bh_b + (rB3 + kk) * 4);
            ldsm_x4(bfl[0][0], bfl[0][1], bfl[1][0], bfl[1][1], bl_b + (rB0 + kk) * 4);
            ldsm_x4(bfl[2][0], bfl[2][1], bfl[3][0], bfl[3][1], bl_b + (rB1 + kk) * 4);
            ldsm_x4(bfl[4][0], bfl[4][1], bfl[5][0], bfl[5][1], bl_b + (rB2 + kk) * 4);
            ldsm_x4(bfl[6][0], bfl[6][1], bfl[7][0], bfl[7][1], bl_b + (rB3 + kk) * 4);
#pragma unroll
            for (int mt = 0; mt < 2; mt++)
#pragma unroll
                for (int nt = 0; nt < 8; nt++) {
                    mma_tf32(acc[mt][nt], afl[mt], bfh[nt]);
                    mma_tf32(acc[mt][nt], afh[mt], bfl[nt]);
                    mma_tf32(acc[mt][nt], afh[mt], bfh[nt]);
                }
        }
        if (nxt < K) {
            __syncthreads();
            sts();
            __syncthreads();
        }
    }

    // epilogue
#pragma unroll
    for (int mt = 0; mt < 2; mt++) {
#pragma unroll
        for (int nt = 0; nt < 8; nt++) {
            int row = m0 + wm + mt * 16 + gid;
            int col = n0 + wn + nt * 8 + tig * 2;
            if (col < N) {
#pragma unroll
                for (int half = 0; half < 2; half++) {
                    int r = row + half * 8;
                    float v0 = acc[mt][nt][half * 2 + 0];
                    float v1 = acc[mt][nt][half * 2 + 1];
                    size_t idx = (size_t)r * ldc + col;
                    if (ACC) {
                        float2 old = *(const float2*)(C + idx);
                        v0 += old.x; v1 += old.y;
                    }
                    if (bias) {
                        v0 += __ldg(bias + col);
                        v1 += __ldg(bias + col + 1);
                    }
                    if (act == 1) { v0 = fmaxf(v0, 0.f); v1 = fmaxf(v1, 0.f); }
                    else if (act == 2) {
                        v0 = 1.f / (1.f + __expf(-v0));
                        v1 = 1.f / (1.f + __expf(-v1));
                    }
                    *(float2*)(C + idx) = make_float2(v0, v1);
                }
            }
        }
    }
}

// ---------------- elementwise kernels ----------------
__global__ void init_kernel(const float* __restrict__ h_in,
                            float* __restrict__ h, float* __restrict__ mask)
{
    int row = blockIdx.x;
    int t = threadIdx.x;   // 128
    float v = h_in[(size_t)row * FIN + t];
    float s = fabsf(v);
#pragma unroll
    for (int o = 16; o; o >>= 1) s += __shfl_xor_sync(0xffffffffu, s, o);
    __shared__ float ws[4];
    if ((t & 31) == 0) ws[t >> 5] = s;
    __syncthreads();
    if (t == 0) {
        float tot = ws[0] + ws[1] + ws[2] + ws[3];
        mask[row] = (tot > 0.f) ? 1.f : 0.f;
    }
    float* hr = h + (size_t)row * HH;
    hr[t]         = v;
    hr[t + 128]   = 0.f;
    hr[t + 256]   = 0.f;
    hr[t + 384]   = 0.f;
}

__global__ void agg_kernel(const float* __restrict__ e,
                           const float* __restrict__ hproj,
                           float* __restrict__ m)
{
    int row = blockIdx.x;          // b*128 + v
    int b = row >> 7;
    int t = threadIdx.x;           // 128
    __shared__ int cnt;
    __shared__ int widx[NN];
    __shared__ int wlab[NN];
    if (t == 0) cnt = 0;
    __syncthreads();
    float ev = e[(size_t)row * NN + t];
    int lab = (int)(ev + 0.5f);
    if (lab >= 1) {
        int p = atomicAdd(&cnt, 1);
        widx[p] = t;
        wlab[p] = lab - 1;
    }
    __syncthreads();
    float a0 = 0.f, a1 = 0.f, a2 = 0.f, a3 = 0.f;
    int n = cnt;
    const float* hb = hproj + (size_t)b * LL * NN * MSGD;
    for (int i = 0; i < n; i++) {
        const float* src = hb + ((size_t)wlab[i] * NN + widx[i]) * MSGD;
        a0 += __ldg(src + t);
        a1 += __ldg(src + t + 128);
        a2 += __ldg(src + t + 256);
        a3 += __ldg(src + t + 384);
    }
    float* o = m + (size_t)row * MSGD;
    o[t]       = a0;
    o[t + 128] = a1;
    o[t + 256] = a2;
    o[t + 384] = a3;
}

__global__ void gru_kernel(float* __restrict__ h,
                           const float* __restrict__ gi,
                           const float* __restrict__ gh,
                           const float* __restrict__ mask)
{
    int row = blockIdx.x;
    int t = threadIdx.x;   // 128
    float mk = mask[row];
    const float* gir = gi + (size_t)row * 3 * HH;
    const float* ghr = gh + (size_t)row * 3 * HH;
    float* hr = h + (size_t)row * HH;
#pragma unroll
    for (int j = 0; j < 4; j++) {
        int idx = t + j * 128;
        float ir = gir[idx], iz = gir[idx + HH], in_ = gir[idx + 2 * HH];
        float hrv = ghr[idx], hz = ghr[idx + HH], hn = ghr[idx + 2 * HH];
        float r  = 1.f / (1.f + __expf(-(ir + hrv)));
        float z  = 1.f / (1.f + __expf(-(iz + hz)));
        float nn = tanhf(in_ + r * hn);
        float ho = hr[idx];
        hr[idx] = ((1.f - z) * nn + z * ho) * mk;
    }
}

__global__ void reduce_kernel(const float* __restrict__ gate,
                              const float* __restrict__ val,
                              const float* __restrict__ mask,
                              float* __restrict__ out)
{
    __shared__ float sm[TGT][NN];
    int b = blockIdx.x;
    int t = threadIdx.x;   // 128
    int row = b * NN + t;
    float mk = mask[row];
#pragma unroll
    for (int j = 0; j < TGT; j++)
        sm[j][t] = gate[(size_t)row * TGT + j] * val[(size_t)row * TGT + j] * mk;
    __syncthreads();
    for (int s = 64; s > 0; s >>= 1) {
        if (t < s) {
#pragma unroll
            for (int j = 0; j < TGT; j++) sm[j][t] += sm[j][t + s];
        }
        __syncthreads();
    }
    if (t < TGT) out[b * TGT + t] = sm[t][0];
}

// ---------------- host side ----------------
static void gemm(const float* A, int lda, const float* B, int ldb,
                 float* C, int ldc, int M, int N, int K,
                 const float* bias, int act, bool transb, bool acc,
                 int batches = 1, int dv = 1,
                 long long aHi = 0, long long aLo = 0,
                 long long bHi = 0, long long bLo = 0,
                 long long cHi = 0, long long cLo = 0)
{
    dim3 grid((N + 127) / 128, M / 128, batches);
    if (transb) {
        if (acc) tgemm_kernel<true , true ><<<grid, 256>>>(A, lda, B, ldb, C, ldc, M, N, K, bias, act, dv, aHi, aLo, bHi, bLo, cHi, cLo);
        else     tgemm_kernel<true , false><<<grid, 256>>>(A, lda, B, ldb, C, ldc, M, N, K, bias, act, dv, aHi, aLo, bHi, bLo, cHi, cLo);
    } else {
        if (acc) tgemm_kernel<false, true ><<<grid, 256>>>(A, lda, B, ldb, C, ldc, M, N, K, bias, act, dv, aHi, aLo, bHi, bLo, cHi, cLo);
        else     tgemm_kernel<false, false><<<grid, 256>>>(A, lda, B, ldb, C, ldc, M, N, K, bias, act, dv, aHi, aLo, bHi, bLo, cHi, cLo);
    }
}

extern "C" void kernel_launch(void* const* d_in, const int* in_sizes, int n_in,
                              void* d_out, int out_size)
{
    const float* h_in  = (const float*)d_in[1];
    const float* e     = (const float*)d_in[2];
    const float* Amat  = (const float*)d_in[3];
    const float* Wih   = (const float*)d_in[4];
    const float* Whh   = (const float*)d_in[5];
    const float* bih   = (const float*)d_in[6];
    const float* bhh   = (const float*)d_in[7];

    const float *r1W[4], *r1b[4], *r2W[4], *r2b[4];
    if (in_sizes[10] == 65536) {
        for (int i = 0; i < 4; i++) {
            r1W[i] = (const float*)d_in[8 + 4 * i];
            r1b[i] = (const float*)d_in[9 + 4 * i];
            r2W[i] = (const float*)d_in[10 + 4 * i];
            r2b[i] = (const float*)d_in[11 + 4 * i];
        }
    } else {
        for (int i = 0; i < 4; i++) {
            r1W[i] = (const float*)d_in[8 + 2 * i];
            r1b[i] = (const float*)d_in[9 + 2 * i];
            r2W[i] = (const float*)d_in[16 + 2 * i];
            r2b[i] = (const float*)d_in[17 + 2 * i];
        }
    }
    float* out = (float*)d_out;

    float *h_, *hproj, *m_, *gi, *gh, *mask, *t0, *t1, *gate, *val;
    cudaGetSymbolAddress((void**)&h_,    g_h);
    cudaGetSymbolAddress((void**)&hproj, g_hproj);
    cudaGetSymbolAddress((void**)&m_,    g_m);
    cudaGetSymbolAddress((void**)&gi,    g_gi);
    cudaGetSymbolAddress((void**)&gh,    g_gh);
    cudaGetSymbolAddress((void**)&mask,  g_mask);
    cudaGetSymbolAddress((void**)&t0,    g_t0);
    cudaGetSymbolAddress((void**)&t1,    g_t1);
    cudaGetSymbolAddress((void**)&gate,  g_gate);
    cudaGetSymbolAddress((void**)&val,   g_val);

    init_kernel<<<ROWS, 128>>>(h_in, h_, mask);

    for (int step = 0; step < 4; step++) {
        // hproj[b,l] = h[b] @ A[l]   (256 batched 128x512x512)
        gemm(h_, HH, Amat, MSGD, hproj, MSGD,
             NN, MSGD, HH, nullptr, 0, /*transb=*/false, /*acc=*/false,
             /*batches=*/BQ * LL, /*dv=*/LL,
             (long long)NN * HH, 0,
             0, (long long)HH * MSGD,
             (long long)LL * NN * MSGD, (long long)NN * MSGD);

        agg_kernel<<<ROWS, 128>>>(e, hproj, m_);

        gemm(m_, MSGD, Wih, MSGD, gi, 3 * HH, ROWS, 3 * HH, MSGD, bih, 0, true, false);
        gemm(h_, HH,   Whh, HH,   gh, 3 * HH, ROWS, 3 * HH, HH,   bhh, 0, true, false);

        gru_kernel<<<ROWS, 128>>>(h_, gi, gh, mask);
    }

    // gate chain: relu(concat(h,h0) @ W0^T + b0) as two GEMMs (h0 tail = h_in pad)
    gemm(h_,   HH,  r1W[0],      2 * HH, t0, 128, ROWS, 128, HH,  nullptr, 0, true, false);
    gemm(h_in, FIN, r1W[0] + HH, 2 * HH, t0, 128, ROWS, 128, FIN, r1b[0],  1, true, true);
    gemm(t0, 128, r1W[1], 128, t1, 256, ROWS, 256, 128, r1b[1], 1, true, false);
    gemm(t1, 256, r1W[2], 256, t0, 128, ROWS, 128, 256, r1b[2], 1, true, false);
    gemm(t0, 128, r1W[3], 128, gate, TGT, ROWS, TGT, 128, r1b[3], 2, true, false);

    // val chain
    gemm(h_, HH,  r2W[0], HH,  t0, 128, ROWS, 128, HH,  r2b[0], 1, true, false);
    gemm(t0, 128, r2W[1], 128, t1, 256, ROWS, 256, 128, r2b[1], 1, true, false);
    gemm(t1, 256, r2W[2], 256, t0, 128, ROWS, 128, 256, r2b[2], 1, true, false);
    gemm(t0, 128, r2W[3], 128, val, TGT, ROWS, TGT, 128, r2b[3], 0, true, false);

    reduce_kernel<<<BQ, 128>>>(gate, val, mask, out);
}

// round 9
// speedup vs baseline: 1.1815x; 1.1815x over previous
#include <cuda_runtime.h>
#include <cstdint>

// Problem constants
#define BQ   64
#define NN   128
#define FIN  128
#define HH   512
#define MSGD 512
#define LL   4
#define ROWS (BQ*NN)      // 8192
#define TGT  12

// ---------------- scratch (device globals) ----------------
__device__ float g_h    [ROWS*HH];
__device__ float g_hproj[BQ*LL*NN*MSGD];
__device__ float g_m    [ROWS*MSGD];
__device__ float g_gi   [ROWS*3*HH];
__device__ float g_gh   [ROWS*3*HH];
__device__ float g_mask [ROWS];
__device__ float g_t0   [ROWS*256];
__device__ float g_t1   [ROWS*256];
__device__ float g_gate [ROWS*TGT];
__device__ float g_val  [ROWS*TGT];

// ---------------- tf32x3 helpers ----------------
__device__ __forceinline__ uint32_t f2tf(float x) {
    uint32_t r;
    asm("cvt.rna.tf32.f32 %0, %1;" : "=r"(r) : "f"(x));
    return r;
}
__device__ __forceinline__ void tfsplit(float x, uint32_t& hi, uint32_t& lo) {
    hi = f2tf(x);
    float hf = __uint_as_float(hi);
    lo = f2tf(x - hf);
}
__device__ __forceinline__ void mma_tf32(float* d, const uint32_t* a, const uint32_t* b) {
    asm volatile(
        "mma.sync.aligned.m16n8k8.row.col.f32.tf32.tf32.f32 "
        "{%0,%1,%2,%3}, {%4,%5,%6,%7}, {%8,%9}, {%0,%1,%2,%3};\n"
        : "+f"(d[0]), "+f"(d[1]), "+f"(d[2]), "+f"(d[3])
        : "r"(a[0]), "r"(a[1]), "r"(a[2]), "r"(a[3]), "r"(b[0]), "r"(b[1]));
}
__device__ __forceinline__ void ldsm_x4(uint32_t& r0, uint32_t& r1, uint32_t& r2, uint32_t& r3,
                                        uint32_t addr) {
    asm volatile("ldmatrix.sync.aligned.m8n8.x4.shared.b16 {%0,%1,%2,%3}, [%4];"
                 : "=r"(r0), "=r"(r1), "=r"(r2), "=r"(r3) : "r"(addr));
}

#define LDT 20   // smem row stride in words

// ================= BIG kernel: 128x128, double-buffered dynamic smem =================
#define PLANE  (128 * LDT)        // 2560 words
#define BUFW   (4 * PLANE)        // Ah,Al,Bh,Bl = 10240 words
#define BIG_SMEM_BYTES (2 * BUFW * 4)  // 81920 B

template<bool TRANSB>
__global__ void __launch_bounds__(256)
tgemm_big(const float* __restrict__ A, int lda,
          const float* __restrict__ Bm, int ldb,
          float* __restrict__ C, int ldc,
          int M, int N, int K,
          const float* __restrict__ bias, int act,
          int dv,
          long long aHi, long long aLo,
          long long bHi, long long bLo,
          long long cHi, long long cLo)
{
    extern __shared__ uint32_t smw[];

    int z = blockIdx.z;
    int zh = z / dv, zl = z % dv;
    A  += zh*aHi + zl*aLo;
    Bm += zh*bHi + zl*bLo;
    C  += zh*cHi + zl*cLo;

    int tid  = threadIdx.x;
    int lane = tid & 31;
    int wid  = tid >> 5;
    int gid  = lane >> 2;
    int tig  = lane & 3;
    int quad = lane >> 3;
    int rowin= lane & 7;
    int wm   = (wid & 3) * 32;
    int wn   = (wid >> 2) * 64;
    int m0   = blockIdx.y * 128;
    int n0   = blockIdx.x * 128;

    uint32_t sbase = (uint32_t)__cvta_generic_to_shared(smw);

    // ldmatrix lane-address row offsets (words, within a plane)
    int rA0 = (wm + ((quad & 1) << 3) + rowin) * LDT + ((quad >> 1) << 2);
    int rA1 = rA0 + 16 * LDT;
    int rB0 = (wn + ((quad >> 1) << 3) + rowin) * LDT + ((quad & 1) << 2);
    int rB1 = rB0 + 16 * LDT;
    int rB2 = rB0 + 32 * LDT;
    int rB3 = rB0 + 48 * LDT;

    float4 aS[2], bS[2];
    const float4 f4z = make_float4(0.f, 0.f, 0.f, 0.f);

    auto ldg = [&](int k0) {
#pragma unroll
        for (int i = 0; i < 2; i++) {
            int f = i * 256 + tid;
            int r = f >> 2;
            int kq = (f & 3) * 4;
            aS[i] = *(const float4*)(A + (size_t)(m0 + r) * lda + k0 + kq);
            if (TRANSB) {
                int n = n0 + r;
                bS[i] = (n < N) ? *(const float4*)(Bm + (size_t)n * ldb + k0 + kq) : f4z;
            } else {
                int rr = f >> 5;
                int c = (f & 31) * 4;
                int n = n0 + c;
                bS[i] = (n < N) ? *(const float4*)(Bm + (size_t)(k0 + rr) * ldb + n) : f4z;
            }
        }
    };
    auto sts = [&](int buf) {
        uint32_t* Ah = smw + buf * BUFW;
        uint32_t* Al = Ah + PLANE;
        uint32_t* Bh = Al + PLANE;
        uint32_t* Bl = Bh + PLANE;
#pragma unroll
        for (int i = 0; i < 2; i++) {
            int f = i * 256 + tid;
            int r = f >> 2;
            int kq = (f & 3) * 4;
            float av[4] = {aS[i].x, aS[i].y, aS[i].z, aS[i].w};
            uint32_t h4[4], l4[4];
#pragma unroll
            for (int q = 0; q < 4; q++) tfsplit(av[q], h4[q], l4[q]);
            *(uint4*)&Ah[r * LDT + kq] = make_uint4(h4[0], h4[1], h4[2], h4[3]);
            *(uint4*)&Al[r * LDT + kq] = make_uint4(l4[0], l4[1], l4[2], l4[3]);

            float bv[4] = {bS[i].x, bS[i].y, bS[i].z, bS[i].w};
            if (TRANSB) {
#pragma unroll
                for (int q = 0; q < 4; q++) tfsplit(bv[q], h4[q], l4[q]);
                *(uint4*)&Bh[r * LDT + kq] = make_uint4(h4[0], h4[1], h4[2], h4[3]);
                *(uint4*)&Bl[r * LDT + kq] = make_uint4(l4[0], l4[1], l4[2], l4[3]);
            } else {
                int rr = f >> 5;
                int c = (f & 31) * 4;
#pragma unroll
                for (int q = 0; q < 4; q++) {
                    uint32_t h, l;
                    tfsplit(bv[q], h, l);
                    Bh[(c + q) * LDT + rr] = h;
                    Bl[(c + q) * LDT + rr] = l;
                }
            }
        }
    };

    float acc[2][8][4];
#pragma unroll
    for (int mt = 0; mt < 2; mt++)
#pragma unroll
        for (int nt = 0; nt < 8; nt++)
#pragma unroll
            for (int q = 0; q < 4; q++) acc[mt][nt][q] = 0.f;

    ldg(0);
    sts(0);
    __syncthreads();

    int cur = 0;
    for (int k0 = 0; k0 < K; k0 += 16) {
        int nxt = k0 + 16;
        if (nxt < K) ldg(nxt);
        uint32_t ah_c = sbase + (cur * BUFW) * 4;
        uint32_t al_c = ah_c + PLANE * 4;
        uint32_t bh_c = al_c + PLANE * 4;
        uint32_t bl_c = bh_c + PLANE * 4;
#pragma unroll
        for (int kk = 0; kk < 16; kk += 8) {
            uint32_t afh[2][4], afl[2][4], bfh[8][2], bfl[8][2];
            ldsm_x4(afh[0][0], afh[0][1], afh[0][2], afh[0][3], ah_c + (rA0 + kk) * 4);
            ldsm_x4(afh[1][0], afh[1][1], afh[1][2], afh[1][3], ah_c + (rA1 + kk) * 4);
            ldsm_x4(afl[0][0], afl[0][1], afl[0][2], afl[0][3], al_c + (rA0 + kk) * 4);
            ldsm_x4(afl[1][0], afl[1][1], afl[1][2], afl[1][3], al_c + (rA1 + kk) * 4);
            ldsm_x4(bfh[0][0], bfh[0][1], bfh[1][0], bfh[1][1], bh_c + (rB0 + kk) * 4);
            ldsm_x4(bfh[2][0], bfh[2][1], bfh[3][0], bfh[3][1], bh_c + (rB1 + kk) * 4);
            ldsm_x4(bfh[4][0], bfh[4][1], bfh[5][0], bfh[5][1], bh_c + (rB2 + kk) * 4);
            ldsm_x4(bfh[6][0], bfh[6][1], bfh[7][0], bfh[7][1], bh_c + (rB3 + kk) * 4);
            ldsm_x4(bfl[0][0], bfl[0][1], bfl[1][0], bfl[1][1], bl_c + (rB0 + kk) * 4);
            ldsm_x4(bfl[2][0], bfl[2][1], bfl[3][0], bfl[3][1], bl_c + (rB1 + kk) * 4);
            ldsm_x4(bfl[4][0], bfl[4][1], bfl[5][0], bfl[5][1], bl_c + (rB2 + kk) * 4);
            ldsm_x4(bfl[6][0], bfl[6][1], bfl[7][0], bfl[7][1], bl_c + (rB3 + kk) * 4);
#pragma unroll
            for (int mt = 0; mt < 2; mt++)
#pragma unroll
                for (int nt = 0; nt < 8; nt++) {
                    mma_tf32(acc[mt][nt], afl[mt], bfh[nt]);
                    mma_tf32(acc[mt][nt], afh[mt], bfl[nt]);
                    mma_tf32(acc[mt][nt], afh[mt], bfh[nt]);
                }
        }
        if (nxt < K) {
            sts(cur ^ 1);          // writes other buffer; everyone done reading it (last sync)
            __syncthreads();       // ONE barrier per tile
            cur ^= 1;
        }
    }

#pragma unroll
    for (int mt = 0; mt < 2; mt++) {
#pragma unroll
        for (int nt = 0; nt < 8; nt++) {
            int row = m0 + wm + mt * 16 + gid;
            int col = n0 + wn + nt * 8 + tig * 2;
            if (col < N) {
#pragma unroll
                for (int half = 0; half < 2; half++) {
                    int r = row + half * 8;
                    float v0 = acc[mt][nt][half * 2 + 0];
                    float v1 = acc[mt][nt][half * 2 + 1];
                    size_t idx = (size_t)r * ldc + col;
                    if (bias) {
                        v0 += __ldg(bias + col);
                        v1 += __ldg(bias + col + 1);
                    }
                    *(float2*)(C + idx) = make_float2(v0, v1);
                }
            }
        }
    }
}

// ================= MLP kernel: 128x64, static smem, 2 CTAs/SM (R7 config) =================
template<bool ACC>
__global__ void __launch_bounds__(256, 2)
tgemm_mlp(const float* __restrict__ A, int lda,
          const float* __restrict__ Bm, int ldb,
          float* __restrict__ C, int ldc,
          int M, int N, int K,
          const float* __restrict__ bias, int act)
{
    __shared__ uint32_t Ah[128 * LDT], Al[128 * LDT];
    __shared__ uint32_t Bh[64 * LDT],  Bl[64 * LDT];

    int tid  = threadIdx.x;
    int lane = tid & 31;
    int wid  = tid >> 5;
    int gid  = lane >> 2;
    int tig  = lane & 3;
    int quad = lane >> 3;
    int rowin= lane & 7;
    int wm   = (wid & 3) * 32;
    int wn   = (wid >> 2) * 32;
    int m0   = blockIdx.y * 128;
    int n0   = blockIdx.x * 64;

    uint32_t ah_b = (uint32_t)__cvta_generic_to_shared(Ah);
    uint32_t al_b = (uint32_t)__cvta_generic_to_shared(Al);
    uint32_t bh_b = (uint32_t)__cvta_generic_to_shared(Bh);
    uint32_t bl_b = (uint32_t)__cvta_generic_to_shared(Bl);

    int rA0 = (wm + ((quad & 1) << 3) + rowin) * LDT + ((quad >> 1) << 2);
    int rA1 = rA0 + 16 * LDT;
    int rB0 = (wn + ((quad >> 1) << 3) + rowin) * LDT + ((quad & 1) << 2);
    int rB1 = rB0 + 16 * LDT;

    float4 aS[2], bS;
    const float4 f4z = make_float4(0.f, 0.f, 0.f, 0.f);

    auto ldg = [&](int k0) {
#pragma unroll
        for (int i = 0; i < 2; i++) {
            int f = i * 256 + tid;
            int r = f >> 2;
            int kq = (f & 3) * 4;
            aS[i] = *(const float4*)(A + (size_t)(m0 + r) * lda + k0 + kq);
        }
        int r = tid >> 2;
        int kq = (tid & 3) * 4;
        int n = n0 + r;
        bS = (n < N) ? *(const float4*)(Bm + (size_t)n * ldb + k0 + kq) : f4z;
    };
    auto sts = [&]() {
#pragma unroll
        for (int i = 0; i < 2; i++) {
            int f = i * 256 + tid;
            int r = f >> 2;
            int kq = (f & 3) * 4;
            float av[4] = {aS[i].x, aS[i].y, aS[i].z, aS[i].w};
            uint32_t h4[4], l4[4];
#pragma unroll
            for (int q = 0; q < 4; q++) tfsplit(av[q], h4[q], l4[q]);
            *(uint4*)&Ah[r * LDT + kq] = make_uint4(h4[0], h4[1], h4[2], h4[3]);
            *(uint4*)&Al[r * LDT + kq] = make_uint4(l4[0], l4[1], l4[2], l4[3]);
        }
        {
            int r = tid >> 2;
            int kq = (tid & 3) * 4;
            float bv[4] = {bS.x, bS.y, bS.z, bS.w};
            uint32_t h4[4], l4[4];
#pragma unroll
            for (int q = 0; q < 4; q++) tfsplit(bv[q], h4[q], l4[q]);
            *(uint4*)&Bh[r * LDT + kq] = make_uint4(h4[0], h4[1], h4[2], h4[3]);
            *(uint4*)&Bl[r * LDT + kq] = make_uint4(l4[0], l4[1], l4[2], l4[3]);
        }
    };

    float acc[2][4][4];
#pragma unroll
    for (int mt = 0; mt < 2; mt++)
#pragma unroll
        for (int nt = 0; nt < 4; nt++)
#pragma unroll
            for (int q = 0; q < 4; q++) acc[mt][nt][q] = 0.f;

    ldg(0);
    sts();
    __syncthreads();

    for (int k0 = 0; k0 < K; k0 += 16) {
        int nxt = k0 + 16;
        if (nxt < K) ldg(nxt);
#pragma unroll
        for (int kk = 0; kk < 16; kk += 8) {
            uint32_t afh[2][4], afl[2][4], bfh[4][2], bfl[4][2];
            ldsm_x4(afh[0][0], afh[0][1], afh[0][2], afh[0][3], ah_b + (rA0 + kk) * 4);
            ldsm_x4(afh[1][0], afh[1][1], afh[1][2], afh[1][3], ah_b + (rA1 + kk) * 4);
            ldsm_x4(afl[0][0], afl[0][1], afl[0][2], afl[0][3], al_b + (rA0 + kk) * 4);
            ldsm_x4(afl[1][0], afl[1][1], afl[1][2], afl[1][3], al_b + (rA1 + kk) * 4);
            ldsm_x4(bfh[0][0], bfh[0][1], bfh[1][0], bfh[1][1], bh_b + (rB0 + kk) * 4);
            ldsm_x4(bfh[2][0], bfh[2][1], bfh[3][0], bfh[3][1], bh_b + (rB1 + kk) * 4);
            ldsm_x4(bfl[0][0], bfl[0][1], bfl[1][0], bfl[1][1], bl_b + (rB0 + kk) * 4);
            ldsm_x4(bfl[2][0], bfl[2][1], bfl[3][0], bfl[3][1], bl_b + (rB1 + kk) * 4);
#pragma unroll
            for (int mt = 0; mt < 2; mt++)
#pragma unroll
                for (int nt = 0; nt < 4; nt++) {
                    mma_tf32(acc[mt][nt], afl[mt], bfh[nt]);
                    mma_tf32(acc[mt][nt], afh[mt], bfl[nt]);
                    mma_tf32(acc[mt][nt], afh[mt], bfh[nt]);
                }
        }
        if (nxt < K) {
            __syncthreads();
            sts();
            __syncthreads();
        }
    }

#pragma unroll
    for (int mt = 0; mt < 2; mt++) {
#pragma unroll
        for (int nt = 0; nt < 4; nt++) {
            int row = m0 + wm + mt * 16 + gid;
            int col = n0 + wn + nt * 8 + tig * 2;
            if (col < N) {
#pragma unroll
                for (int half = 0; half < 2; half++) {
                    int r = row + half * 8;
                    float v0 = acc[mt][nt][half * 2 + 0];
                    float v1 = acc[mt][nt][half * 2 + 1];
                    size_t idx = (size_t)r * ldc + col;
                    if (ACC) {
                        float2 old = *(const float2*)(C + idx);
                        v0 += old.x; v1 += old.y;
                    }
                    if (bias) {
                        v0 += __ldg(bias + col);
                        v1 += __ldg(bias + col + 1);
                    }
                    if (act == 1) { v0 = fmaxf(v0, 0.f); v1 = fmaxf(v1, 0.f); }
                    else if (act == 2) {
                        v0 = 1.f / (1.f + __expf(-v0));
                        v1 = 1.f / (1.f + __expf(-v1));
                    }
                    *(float2*)(C + idx) = make_float2(v0, v1);
                }
            }
        }
    }
}

// ---------------- elementwise kernels ----------------
__global__ void init_kernel(const float* __restrict__ h_in,
                            float* __restrict__ h, float* __restrict__ mask)
{
    int row = blockIdx.x;
    int t = threadIdx.x;   // 128
    float v = h_in[(size_t)row * FIN + t];
    float s = fabsf(v);
#pragma unroll
    for (int o = 16; o; o >>= 1) s += __shfl_xor_sync(0xffffffffu, s, o);
    __shared__ float ws[4];
    if ((t & 31) == 0) ws[t >> 5] = s;
    __syncthreads();
    if (t == 0) {
        float tot = ws[0] + ws[1] + ws[2] + ws[3];
        mask[row] = (tot > 0.f) ? 1.f : 0.f;
    }
    float* hr = h + (size_t)row * HH;
    hr[t]         = v;
    hr[t + 128]   = 0.f;
    hr[t + 256]   = 0.f;
    hr[t + 384]   = 0.f;
}

__global__ void agg_kernel(const float* __restrict__ e,
                           const float* __restrict__ hproj,
                           float* __restrict__ m)
{
    int row = blockIdx.x;          // b*128 + v
    int b = row >> 7;
    int t = threadIdx.x;           // 128
    __shared__ int cnt;
    __shared__ int widx[NN];
    __shared__ int wlab[NN];
    if (t == 0) cnt = 0;
    __syncthreads();
    float ev = e[(size_t)row * NN + t];
    int lab = (int)(ev + 0.5f);
    if (lab >= 1) {
        int p = atomicAdd(&cnt, 1);
        widx[p] = t;
        wlab[p] = lab - 1;
    }
    __syncthreads();
    float a0 = 0.f, a1 = 0.f, a2 = 0.f, a3 = 0.f;
    int n = cnt;
    const float* hb = hproj + (size_t)b * LL * NN * MSGD;
    for (int i = 0; i < n; i++) {
        const float* src = hb + ((size_t)wlab[i] * NN + widx[i]) * MSGD;
        a0 += __ldg(src + t);
        a1 += __ldg(src + t + 128);
        a2 += __ldg(src + t + 256);
        a3 += __ldg(src + t + 384);
    }
    float* o = m + (size_t)row * MSGD;
    o[t]       = a0;
    o[t + 128] = a1;
    o[t + 256] = a2;
    o[t + 384] = a3;
}

__global__ void gru_kernel(float* __restrict__ h,
                           const float* __restrict__ gi,
                           const float* __restrict__ gh,
                           const float* __restrict__ mask)
{
    int row = blockIdx.x;
    int t = threadIdx.x;   // 128
    float mk = mask[row];
    const float* gir = gi + (size_t)row * 3 * HH;
    const float* ghr = gh + (size_t)row * 3 * HH;
    float* hr = h + (size_t)row * HH;
#pragma unroll
    for (int j = 0; j < 4; j++) {
        int idx = t + j * 128;
        float ir = gir[idx], iz = gir[idx + HH], in_ = gir[idx + 2 * HH];
        float hrv = ghr[idx], hz = ghr[idx + HH], hn = ghr[idx + 2 * HH];
        float r  = 1.f / (1.f + __expf(-(ir + hrv)));
        float z  = 1.f / (1.f + __expf(-(iz + hz)));
        float nn = tanhf(in_ + r * hn);
        float ho = hr[idx];
        hr[idx] = ((1.f - z) * nn + z * ho) * mk;
    }
}

__global__ void reduce_kernel(const float* __restrict__ gate,
                              const float* __restrict__ val,
                              const float* __restrict__ mask,
                              float* __restrict__ out)
{
    __shared__ float sm[TGT][NN];
    int b = blockIdx.x;
    int t = threadIdx.x;   // 128
    int row = b * NN + t;
    float mk = mask[row];
#pragma unroll
    for (int j = 0; j < TGT; j++)
        sm[j][t] = gate[(size_t)row * TGT + j] * val[(size_t)row * TGT + j] * mk;
    __syncthreads();
    for (int s = 64; s > 0; s >>= 1) {
        if (t < s) {
#pragma unroll
            for (int j = 0; j < TGT; j++) sm[j][t] += sm[j][t + s];
        }
        __syncthreads();
    }
    if (t < TGT) out[b * TGT + t] = sm[t][0];
}

// ---------------- host side ----------------
static void gemm_big_l(const float* A, int lda, const float* B, int ldb,
                       float* C, int ldc, int M, int N, int K,
                       const float* bias, bool transb,
                       int batches = 1, int dv = 1,
                       long long aHi = 0, long long aLo = 0,
                       long long bHi = 0, long long bLo = 0,
                       long long cHi = 0, long long cLo = 0)
{
    dim3 grid((N + 127) / 128, M / 128, batches);
    if (transb)
        tgemm_big<true ><<<grid, 256, BIG_SMEM_BYTES>>>(A, lda, B, ldb, C, ldc, M, N, K, bias, 0, dv, aHi, aLo, bHi, bLo, cHi, cLo);
    else
        tgemm_big<false><<<grid, 256, BIG_SMEM_BYTES>>>(A, lda, B, ldb, C, ldc, M, N, K, bias, 0, dv, aHi, aLo, bHi, bLo, cHi, cLo);
}

static void gemm_mlp_l(const float* A, int lda, const float* B, int ldb,
                       float* C, int ldc, int M, int N, int K,
                       const float* bias, int act, bool acc)
{
    dim3 grid((N + 63) / 64, M / 128, 1);
    if (acc) tgemm_mlp<true ><<<grid, 256>>>(A, lda, B, ldb, C, ldc, M, N, K, bias, act);
    else     tgemm_mlp<false><<<grid, 256>>>(A, lda, B, ldb, C, ldc, M, N, K, bias, act);
}

extern "C" void kernel_launch(void* const* d_in, const int* in_sizes, int n_in,
                              void* d_out, int out_size)
{
    const float* h_in  = (const float*)d_in[1];
    const float* e     = (const float*)d_in[2];
    const float* Amat  = (const float*)d_in[3];
    const float* Wih   = (const float*)d_in[4];
    const float* Whh   = (const float*)d_in[5];
    const float* bih   = (const float*)d_in[6];
    const float* bhh   = (const float*)d_in[7];

    cudaFuncSetAttribute(tgemm_big<true >, cudaFuncAttributeMaxDynamicSharedMemorySize, BIG_SMEM_BYTES);
    cudaFuncSetAttribute(tgemm_big<false>, cudaFuncAttributeMaxDynamicSharedMemorySize, BIG_SMEM_BYTES);

    const float *r1W[4], *r1b[4], *r2W[4], *r2b[4];
    if (in_sizes[10] == 65536) {
        for (int i = 0; i < 4; i++) {
            r1W[i] = (const float*)d_in[8 + 4 * i];
            r1b[i] = (const float*)d_in[9 + 4 * i];
            r2W[i] = (const float*)d_in[10 + 4 * i];
            r2b[i] = (const float*)d_in[11 + 4 * i];
        }
    } else {
        for (int i = 0; i < 4; i++) {
            r1W[i] = (const float*)d_in[8 + 2 * i];
            r1b[i] = (const float*)d_in[9 + 2 * i];
            r2W[i] = (const float*)d_in[16 + 2 * i];
            r2b[i] = (const float*)d_in[17 + 2 * i];
        }
    }
    float* out = (float*)d_out;

    float *h_, *hproj, *m_, *gi, *gh, *mask, *t0, *t1, *gate, *val;
    cudaGetSymbolAddress((void**)&h_,    g_h);
    cudaGetSymbolAddress((void**)&hproj, g_hproj);
    cudaGetSymbolAddress((void**)&m_,    g_m);
    cudaGetSymbolAddress((void**)&gi,    g_gi);
    cudaGetSymbolAddress((void**)&gh,    g_gh);
    cudaGetSymbolAddress((void**)&mask,  g_mask);
    cudaGetSymbolAddress((void**)&t0,    g_t0);
    cudaGetSymbolAddress((void**)&t1,    g_t1);
    cudaGetSymbolAddress((void**)&gate,  g_gate);
    cudaGetSymbolAddress((void**)&val,   g_val);

    init_kernel<<<ROWS, 128>>>(h_in, h_, mask);

    for (int step = 0; step < 4; step++) {
        // hproj[b,l] = h[b] @ A[l]   (256 batched 128x512x512)
        gemm_big_l(h_, HH, Amat, MSGD, hproj, MSGD,
                   NN, MSGD, HH, nullptr, /*transb=*/false,
                   /*batches=*/BQ * LL, /*dv=*/LL,
                   (long long)NN * HH, 0,
                   0, (long long)HH * MSGD,
                   (long long)LL * NN * MSGD, (long long)NN * MSGD);

        agg_kernel<<<ROWS, 128>>>(e, hproj, m_);

        gemm_big_l(m_, MSGD, Wih, MSGD, gi, 3 * HH, ROWS, 3 * HH, MSGD, bih, true);
        gemm_big_l(h_, HH,   Whh, HH,   gh, 3 * HH, ROWS, 3 * HH, HH,   bhh, true);

        gru_kernel<<<ROWS, 128>>>(h_, gi, gh, mask);
    }

    // gate chain: relu(concat(h,h0) @ W0^T + b0) as two GEMMs (h0 tail = h_in pad)
    gemm_mlp_l(h_,   HH,  r1W[0],      2 * HH, t0, 128, ROWS, 128, HH,  nullptr, 0, false);
    gemm_mlp_l(h_in, FIN, r1W[0] + HH, 2 * HH, t0, 128, ROWS, 128, FIN, r1b[0],  1, true);
    gemm_mlp_l(t0, 128, r1W[1], 128, t1, 256, ROWS, 256, 128, r1b[1], 1, false);
    gemm_mlp_l(t1, 256, r1W[2], 256, t0, 128, ROWS, 128, 256, r1b[2], 1, false);
    gemm_mlp_l(t0, 128, r1W[3], 128, gate, TGT, ROWS, TGT, 128, r1b[3], 2, false);

    // val chain
    gemm_mlp_l(h_, HH,  r2W[0], HH,  t0, 128, ROWS, 128, HH,  r2b[0], 1, false);
    gemm_mlp_l(t0, 128, r2W[1], 128, t1, 256, ROWS, 256, 128, r2b[1], 1, false);
    gemm_mlp_l(t1, 256, r2W[2], 256, t0, 128, ROWS, 128, 256, r2b[2], 1, false);
    gemm_mlp_l(t0, 128, r2W[3], 128, val, TGT, ROWS, TGT, 128, r2b[3], 0, false);

    reduce_kernel<<<BQ, 128>>>(gate, val, mask, out);
}

// round 10
// speedup vs baseline: 1.2632x; 1.0691x over previous
#include <cuda_runtime.h>
#include <cstdint>

// Problem constants
#define BQ   64
#define NN   128
#define FIN  128
#define HH   512
#define MSGD 512
#define LL   4
#define ROWS (BQ*NN)      // 8192
#define TGT  12

// ---------------- scratch (device globals) ----------------
__device__ float g_h    [ROWS*HH];
__device__ float g_hproj[BQ*LL*NN*MSGD];
__device__ float g_m    [ROWS*MSGD];
__device__ float g_gi   [ROWS*3*HH];
__device__ float g_gh   [ROWS*3*HH];
__device__ float g_mask [ROWS];
__device__ float g_t0   [ROWS*256];
__device__ float g_t1   [ROWS*256];
__device__ float g_gate [ROWS*TGT];
__device__ float g_val  [ROWS*TGT];

// ---------------- tf32x3 helpers ----------------
__device__ __forceinline__ uint32_t f2tf(float x) {
    uint32_t r;
    asm("cvt.rna.tf32.f32 %0, %1;" : "=r"(r) : "f"(x));
    return r;
}
__device__ __forceinline__ void tfsplit(float x, uint32_t& hi, uint32_t& lo) {
    hi = f2tf(x);
    float hf = __uint_as_float(hi);
    lo = f2tf(x - hf);
}
__device__ __forceinline__ void mma_tf32(float* d, const uint32_t* a, const uint32_t* b) {
    asm volatile(
        "mma.sync.aligned.m16n8k8.row.col.f32.tf32.tf32.f32 "
        "{%0,%1,%2,%3}, {%4,%5,%6,%7}, {%8,%9}, {%0,%1,%2,%3};\n"
        : "+f"(d[0]), "+f"(d[1]), "+f"(d[2]), "+f"(d[3])
        : "r"(a[0]), "r"(a[1]), "r"(a[2]), "r"(a[3]), "r"(b[0]), "r"(b[1]));
}
__device__ __forceinline__ void ldsm_x4(uint32_t& r0, uint32_t& r1, uint32_t& r2, uint32_t& r3,
                                        uint32_t addr) {
    asm volatile("ldmatrix.sync.aligned.m8n8.x4.shared.b16 {%0,%1,%2,%3}, [%4];"
                 : "=r"(r0), "=r"(r1), "=r"(r2), "=r"(r3) : "r"(addr));
}

#define LDT 20   // smem row stride in words

// ================= BIG kernel: 128x128, double-buffered dynamic smem, 2 CTAs/SM =================
#define PLANE  (128 * LDT)        // 2560 words
#define BUFW   (4 * PLANE)        // Ah,Al,Bh,Bl = 10240 words
#define BIG_SMEM_BYTES (2 * BUFW * 4)  // 81920 B

template<bool TRANSB>
__global__ void __launch_bounds__(256, 2)
tgemm_big(const float* __restrict__ A, int lda,
          const float* __restrict__ Bm, int ldb,
          float* __restrict__ C, int ldc,
          int M, int N, int K,
          const float* __restrict__ bias, int act,
          int dv,
          long long aHi, long long aLo,
          long long bHi, long long bLo,
          long long cHi, long long cLo)
{
    extern __shared__ uint32_t smw[];

    int z = blockIdx.z;
    int zh = z / dv, zl = z % dv;
    A  += zh*aHi + zl*aLo;
    Bm += zh*bHi + zl*bLo;
    C  += zh*cHi + zl*cLo;

    int tid  = threadIdx.x;
    int lane = tid & 31;
    int wid  = tid >> 5;
    int gid  = lane >> 2;
    int tig  = lane & 3;
    int quad = lane >> 3;
    int rowin= lane & 7;
    int wm   = (wid & 3) * 32;
    int wn   = (wid >> 2) * 64;
    int m0   = blockIdx.y * 128;
    int n0   = blockIdx.x * 128;

    uint32_t sbase = (uint32_t)__cvta_generic_to_shared(smw);

    // ldmatrix lane-address row offsets (words, within a plane)
    int rA0 = (wm + ((quad & 1) << 3) + rowin) * LDT + ((quad >> 1) << 2);
    int rA1 = rA0 + 16 * LDT;
    int rB0 = (wn + ((quad >> 1) << 3) + rowin) * LDT + ((quad & 1) << 2);
    int rB1 = rB0 + 16 * LDT;
    int rB2 = rB0 + 32 * LDT;
    int rB3 = rB0 + 48 * LDT;

    float4 aS[2], bS[2];
    const float4 f4z = make_float4(0.f, 0.f, 0.f, 0.f);

    auto ldg = [&](int k0) {
#pragma unroll
        for (int i = 0; i < 2; i++) {
            int f = i * 256 + tid;
            int r = f >> 2;
            int kq = (f & 3) * 4;
            aS[i] = *(const float4*)(A + (size_t)(m0 + r) * lda + k0 + kq);
            if (TRANSB) {
                int n = n0 + r;
                bS[i] = (n < N) ? *(const float4*)(Bm + (size_t)n * ldb + k0 + kq) : f4z;
            } else {
                int rr = f >> 5;
                int c = (f & 31) * 4;
                int n = n0 + c;
                bS[i] = (n < N) ? *(const float4*)(Bm + (size_t)(k0 + rr) * ldb + n) : f4z;
            }
        }
    };
    auto sts = [&](int buf) {
        uint32_t* Ah = smw + buf * BUFW;
        uint32_t* Al = Ah + PLANE;
        uint32_t* Bh = Al + PLANE;
        uint32_t* Bl = Bh + PLANE;
#pragma unroll
        for (int i = 0; i < 2; i++) {
            int f = i * 256 + tid;
            int r = f >> 2;
            int kq = (f & 3) * 4;
            float av[4] = {aS[i].x, aS[i].y, aS[i].z, aS[i].w};
            uint32_t h4[4], l4[4];
#pragma unroll
            for (int q = 0; q < 4; q++) tfsplit(av[q], h4[q], l4[q]);
            *(uint4*)&Ah[r * LDT + kq] = make_uint4(h4[0], h4[1], h4[2], h4[3]);
            *(uint4*)&Al[r * LDT + kq] = make_uint4(l4[0], l4[1], l4[2], l4[3]);

            float bv[4] = {bS[i].x, bS[i].y, bS[i].z, bS[i].w};
            if (TRANSB) {
#pragma unroll
                for (int q = 0; q < 4; q++) tfsplit(bv[q], h4[q], l4[q]);
                *(uint4*)&Bh[r * LDT + kq] = make_uint4(h4[0], h4[1], h4[2], h4[3]);
                *(uint4*)&Bl[r * LDT + kq] = make_uint4(l4[0], l4[1], l4[2], l4[3]);
            } else {
                int rr = f >> 5;
                int c = (f & 31) * 4;
#pragma unroll
                for (int q = 0; q < 4; q++) {
                    uint32_t h, l;
                    tfsplit(bv[q], h, l);
                    Bh[(c + q) * LDT + rr] = h;
                    Bl[(c + q) * LDT + rr] = l;
                }
            }
        }
    };

    float acc[2][8][4];
#pragma unroll
    for (int mt = 0; mt < 2; mt++)
#pragma unroll
        for (int nt = 0; nt < 8; nt++)
#pragma unroll
            for (int q = 0; q < 4; q++) acc[mt][nt][q] = 0.f;

    ldg(0);
    sts(0);
    __syncthreads();

    int cur = 0;
    for (int k0 = 0; k0 < K; k0 += 16) {
        int nxt = k0 + 16;
        if (nxt < K) ldg(nxt);
        uint32_t ah_c = sbase + (cur * BUFW) * 4;
        uint32_t al_c = ah_c + PLANE * 4;
        uint32_t bh_c = al_c + PLANE * 4;
        uint32_t bl_c = bh_c + PLANE * 4;
#pragma unroll
        for (int kk = 0; kk < 16; kk += 8) {
            uint32_t afh[2][4], afl[2][4], bfh[8][2], bfl[8][2];
            ldsm_x4(afh[0][0], afh[0][1], afh[0][2], afh[0][3], ah_c + (rA0 + kk) * 4);
            ldsm_x4(afh[1][0], afh[1][1], afh[1][2], afh[1][3], ah_c + (rA1 + kk) * 4);
            ldsm_x4(afl[0][0], afl[0][1], afl[0][2], afl[0][3], al_c + (rA0 + kk) * 4);
            ldsm_x4(afl[1][0], afl[1][1], afl[1][2], afl[1][3], al_c + (rA1 + kk) * 4);
            ldsm_x4(bfh[0][0], bfh[0][1], bfh[1][0], bfh[1][1], bh_c + (rB0 + kk) * 4);
            ldsm_x4(bfh[2][0], bfh[2][1], bfh[3][0], bfh[3][1], bh_c + (rB1 + kk) * 4);
            ldsm_x4(bfh[4][0], bfh[4][1], bfh[5][0], bfh[5][1], bh_c + (rB2 + kk) * 4);
            ldsm_x4(bfh[6][0], bfh[6][1], bfh[7][0], bfh[7][1], bh_c + (rB3 + kk) * 4);
            ldsm_x4(bfl[0][0], bfl[0][1], bfl[1][0], bfl[1][1], bl_c + (rB0 + kk) * 4);
            ldsm_x4(bfl[2][0], bfl[2][1], bfl[3][0], bfl[3][1], bl_c + (rB1 + kk) * 4);
            ldsm_x4(bfl[4][0], bfl[4][1], bfl[5][0], bfl[5][1], bl_c + (rB2 + kk) * 4);
            ldsm_x4(bfl[6][0], bfl[6][1], bfl[7][0], bfl[7][1], bl_c + (rB3 + kk) * 4);
#pragma unroll
            for (int mt = 0; mt < 2; mt++)
#pragma unroll
                for (int nt = 0; nt < 8; nt++) {
                    mma_tf32(acc[mt][nt], afl[mt], bfh[nt]);
                    mma_tf32(acc[mt][nt], afh[mt], bfl[nt]);
                    mma_tf32(acc[mt][nt], afh[mt], bfh[nt]);
                }
        }
        if (nxt < K) {
            sts(cur ^ 1);          // write other buffer (safe: last sync ended reads)
            __syncthreads();       // ONE barrier per tile
            cur ^= 1;
        }
    }

#pragma unroll
    for (int mt = 0; mt < 2; mt++) {
#pragma unroll
        for (int nt = 0; nt < 8; nt++) {
            int row = m0 + wm + mt * 16 + gid;
            int col = n0 + wn + nt * 8 + tig * 2;
            if (col < N) {
#pragma unroll
                for (int half = 0; half < 2; half++) {
                    int r = row + half * 8;
                    float v0 = acc[mt][nt][half * 2 + 0];
                    float v1 = acc[mt][nt][half * 2 + 1];
                    size_t idx = (size_t)r * ldc + col;
                    if (bias) {
                        v0 += __ldg(bias + col);
                        v1 += __ldg(bias + col + 1);
                    }
                    *(float2*)(C + idx) = make_float2(v0, v1);
                }
            }
        }
    }
}

// ================= MLP kernel: 128x64, static smem, 2 CTAs/SM =================
template<bool ACC>
__global__ void __launch_bounds__(256, 2)
tgemm_mlp(const float* __restrict__ A, int lda,
          const float* __restrict__ Bm, int ldb,
          float* __restrict__ C, int ldc,
          int M, int N, int K,
          const float* __restrict__ bias, int act)
{
    __shared__ uint32_t Ah[128 * LDT], Al[128 * LDT];
    __shared__ uint32_t Bh[64 * LDT],  Bl[64 * LDT];

    int tid  = threadIdx.x;
    int lane = tid & 31;
    int wid  = tid >> 5;
    int gid  = lane >> 2;
    int tig  = lane & 3;
    int quad = lane >> 3;
    int rowin= lane & 7;
    int wm   = (wid & 3) * 32;
    int wn   = (wid >> 2) * 32;
    int m0   = blockIdx.y * 128;
    int n0   = blockIdx.x * 64;

    uint32_t ah_b = (uint32_t)__cvta_generic_to_shared(Ah);
    uint32_t al_b = (uint32_t)__cvta_generic_to_shared(Al);
    uint32_t bh_b = (uint32_t)__cvta_generic_to_shared(Bh);
    uint32_t bl_b = (uint32_t)__cvta_generic_to_shared(Bl);

    int rA0 = (wm + ((quad & 1) << 3) + rowin) * LDT + ((quad >> 1) << 2);
    int rA1 = rA0 + 16 * LDT;
    int rB0 = (wn + ((quad >> 1) << 3) + rowin) * LDT + ((quad & 1) << 2);
    int rB1 = rB0 + 16 * LDT;

    float4 aS[2], bS;
    const float4 f4z = make_float4(0.f, 0.f, 0.f, 0.f);

    auto ldg = [&](int k0) {
#pragma unroll
        for (int i = 0; i < 2; i++) {
            int f = i * 256 + tid;
            int r = f >> 2;
            int kq = (f & 3) * 4;
            aS[i] = *(const float4*)(A + (size_t)(m0 + r) * lda + k0 + kq);
        }
        int r = tid >> 2;
        int kq = (tid & 3) * 4;
        int n = n0 + r;
        bS = (n < N) ? *(const float4*)(Bm + (size_t)n * ldb + k0 + kq) : f4z;
    };
    auto sts = [&]() {
#pragma unroll
        for (int i = 0; i < 2; i++) {
            int f = i * 256 + tid;
            int r = f >> 2;
            int kq = (f & 3) * 4;
            float av[4] = {aS[i].x, aS[i].y, aS[i].z, aS[i].w};
            uint32_t h4[4], l4[4];
#pragma unroll
            for (int q = 0; q < 4; q++) tfsplit(av[q], h4[q], l4[q]);
            *(uint4*)&Ah[r * LDT + kq] = make_uint4(h4[0], h4[1], h4[2], h4[3]);
            *(uint4*)&Al[r * LDT + kq] = make_uint4(l4[0], l4[1], l4[2], l4[3]);
        }
        {
            int r = tid >> 2;
            int kq = (tid & 3) * 4;
            float bv[4] = {bS.x, bS.y, bS.z, bS.w};
            uint32_t h4[4], l4[4];
#pragma unroll
            for (int q = 0; q < 4; q++) tfsplit(bv[q], h4[q], l4[q]);
            *(uint4*)&Bh[r * LDT + kq] = make_uint4(h4[0], h4[1], h4[2], h4[3]);
            *(uint4*)&Bl[r * LDT + kq] = make_uint4(l4[0], l4[1], l4[2], l4[3]);
        }
    };

    float acc[2][4][4];
#pragma unroll
    for (int mt = 0; mt < 2; mt++)
#pragma unroll
        for (int nt = 0; nt < 4; nt++)
#pragma unroll
            for (int q = 0; q < 4; q++) acc[mt][nt][q] = 0.f;

    ldg(0);
    sts();
    __syncthreads();

    for (int k0 = 0; k0 < K; k0 += 16) {
        int nxt = k0 + 16;
        if (nxt < K) ldg(nxt);
#pragma unroll
        for (int kk = 0; kk < 16; kk += 8) {
            uint32_t afh[2][4], afl[2][4], bfh[4][2], bfl[4][2];
            ldsm_x4(afh[0][0], afh[0][1], afh[0][2], afh[0][3], ah_b + (rA0 + kk) * 4);
            ldsm_x4(afh[1][0], afh[1][1], afh[1][2], afh[1][3], ah_b + (rA1 + kk) * 4);
            ldsm_x4(afl[0][0], afl[0][1], afl[0][2], afl[0][3], al_b + (rA0 + kk) * 4);
            ldsm_x4(afl[1][0], afl[1][1], afl[1][2], afl[1][3], al_b + (rA1 + kk) * 4);
            ldsm_x4(bfh[0][0], bfh[0][1], bfh[1][0], bfh[1][1], bh_b + (rB0 + kk) * 4);
            ldsm_x4(bfh[2][0], bfh[2][1], bfh[3][0], bfh[3][1], bh_b + (rB1 + kk) * 4);
            ldsm_x4(bfl[0][0], bfl[0][1], bfl[1][0], bfl[1][1], bl_b + (rB0 + kk) * 4);
            ldsm_x4(bfl[2][0], bfl[2][1], bfl[3][0], bfl[3][1], bl_b + (rB1 + kk) * 4);
#pragma unroll
            for (int mt = 0; mt < 2; mt++)
#pragma unroll
                for (int nt = 0; nt < 4; nt++) {
                    mma_tf32(acc[mt][nt], afl[mt], bfh[nt]);
                    mma_tf32(acc[mt][nt], afh[mt], bfl[nt]);
                    mma_tf32(acc[mt][nt], afh[mt], bfh[nt]);
                }
        }
        if (nxt < K) {
            __syncthreads();
            sts();
            __syncthreads();
        }
    }

#pragma unroll
    for (int mt = 0; mt < 2; mt++) {
#pragma unroll
        for (int nt = 0; nt < 4; nt++) {
            int row = m0 + wm + mt * 16 + gid;
            int col = n0 + wn + nt * 8 + tig * 2;
            if (col < N) {
#pragma unroll
                for (int half = 0; half < 2; half++) {
                    int r = row + half * 8;
                    float v0 = acc[mt][nt][half * 2 + 0];
                    float v1 = acc[mt][nt][half * 2 + 1];
                    size_t idx = (size_t)r * ldc + col;
                    if (ACC) {
                        float2 old = *(const float2*)(C + idx);
                        v0 += old.x; v1 += old.y;
                    }
                    if (bias) {
                        v0 += __ldg(bias + col);
                        v1 += __ldg(bias + col + 1);
                    }
                    if (act == 1) { v0 = fmaxf(v0, 0.f); v1 = fmaxf(v1, 0.f); }
                    else if (act == 2) {
                        v0 = 1.f / (1.f + __expf(-v0));
                        v1 = 1.f / (1.f + __expf(-v1));
                    }
                    *(float2*)(C + idx) = make_float2(v0, v1);
                }
            }
        }
    }
}

// ---------------- elementwise kernels ----------------
__global__ void init_kernel(const float* __restrict__ h_in,
                            float* __restrict__ h, float* __restrict__ mask)
{
    int row = blockIdx.x;
    int t = threadIdx.x;   // 128
    float v = h_in[(size_t)row * FIN + t];
    float s = fabsf(v);
#pragma unroll
    for (int o = 16; o; o >>= 1) s += __shfl_xor_sync(0xffffffffu, s, o);
    __shared__ float ws[4];
    if ((t & 31) == 0) ws[t >> 5] = s;
    __syncthreads();
    if (t == 0) {
        float tot = ws[0] + ws[1] + ws[2] + ws[3];
        mask[row] = (tot > 0.f) ? 1.f : 0.f;
    }
    float* hr = h + (size_t)row * HH;
    hr[t]         = v;
    hr[t + 128]   = 0.f;
    hr[t + 256]   = 0.f;
    hr[t + 384]   = 0.f;
}

__global__ void agg_kernel(const float* __restrict__ e,
                           const float* __restrict__ hproj,
                           float* __restrict__ m)
{
    int row = blockIdx.x;          // b*128 + v
    int b = row >> 7;
    int t = threadIdx.x;           // 128
    __shared__ int cnt;
    __shared__ int widx[NN];
    __shared__ int wlab[NN];
    if (t == 0) cnt = 0;
    __syncthreads();
    float ev = e[(size_t)row * NN + t];
    int lab = (int)(ev + 0.5f);
    if (lab >= 1) {
        int p = atomicAdd(&cnt, 1);
        widx[p] = t;
        wlab[p] = lab - 1;
    }
    __syncthreads();
    float a0 = 0.f, a1 = 0.f, a2 = 0.f, a3 = 0.f;
    int n = cnt;
    const float* hb = hproj + (size_t)b * LL * NN * MSGD;
    for (int i = 0; i < n; i++) {
        const float* src = hb + ((size_t)wlab[i] * NN + widx[i]) * MSGD;
        a0 += __ldg(src + t);
        a1 += __ldg(src + t + 128);
        a2 += __ldg(src + t + 256);
        a3 += __ldg(src + t + 384);
    }
    float* o = m + (size_t)row * MSGD;
    o[t]       = a0;
    o[t + 128] = a1;
    o[t + 256] = a2;
    o[t + 384] = a3;
}

__global__ void gru_kernel(float* __restrict__ h,
                           const float* __restrict__ gi,
                           const float* __restrict__ gh,
                           const float* __restrict__ mask)
{
    int row = blockIdx.x;
    int t = threadIdx.x;   // 128
    float mk = mask[row];
    const float* gir = gi + (size_t)row * 3 * HH;
    const float* ghr = gh + (size_t)row * 3 * HH;
    float* hr = h + (size_t)row * HH;
#pragma unroll
    for (int j = 0; j < 4; j++) {
        int idx = t + j * 128;
        float ir = gir[idx], iz = gir[idx + HH], in_ = gir[idx + 2 * HH];
        float hrv = ghr[idx], hz = ghr[idx + HH], hn = ghr[idx + 2 * HH];
        float r  = 1.f / (1.f + __expf(-(ir + hrv)));
        float z  = 1.f / (1.f + __expf(-(iz + hz)));
        float nn = tanhf(in_ + r * hn);
        float ho = hr[idx];
        hr[idx] = ((1.f - z) * nn + z * ho) * mk;
    }
}

__global__ void reduce_kernel(const float* __restrict__ gate,
                              const float* __restrict__ val,
                              const float* __restrict__ mask,
                              float* __restrict__ out)
{
    __shared__ float sm[TGT][NN];
    int b = blockIdx.x;
    int t = threadIdx.x;   // 128
    int row = b * NN + t;
    float mk = mask[row];
#pragma unroll
    for (int j = 0; j < TGT; j++)
        sm[j][t] = gate[(size_t)row * TGT + j] * val[(size_t)row * TGT + j] * mk;
    __syncthreads();
    for (int s = 64; s > 0; s >>= 1) {
        if (t < s) {
#pragma unroll
            for (int j = 0; j < TGT; j++) sm[j][t] += sm[j][t + s];
        }
        __syncthreads();
    }
    if (t < TGT) out[b * TGT + t] = sm[t][0];
}

// ---------------- host side ----------------
static void gemm_big_l(const float* A, int lda, const float* B, int ldb,
                       float* C, int ldc, int M, int N, int K,
                       const float* bias, bool transb,
                       int batches = 1, int dv = 1,
                       long long aHi = 0, long long aLo = 0,
                       long long bHi = 0, long long bLo = 0,
                       long long cHi = 0, long long cLo = 0)
{
    dim3 grid((N + 127) / 128, M / 128, batches);
    if (transb)
        tgemm_big<true ><<<grid, 256, BIG_SMEM_BYTES>>>(A, lda, B, ldb, C, ldc, M, N, K, bias, 0, dv, aHi, aLo, bHi, bLo, cHi, cLo);
    else
        tgemm_big<false><<<grid, 256, BIG_SMEM_BYTES>>>(A, lda, B, ldb, C, ldc, M, N, K, bias, 0, dv, aHi, aLo, bHi, bLo, cHi, cLo);
}

static void gemm_mlp_l(const float* A, int lda, const float* B, int ldb,
                       float* C, int ldc, int M, int N, int K,
                       const float* bias, int act, bool acc)
{
    dim3 grid((N + 63) / 64, M / 128, 1);
    if (acc) tgemm_mlp<true ><<<grid, 256>>>(A, lda, B, ldb, C, ldc, M, N, K, bias, act);
    else     tgemm_mlp<false><<<grid, 256>>>(A, lda, B, ldb, C, ldc, M, N, K, bias, act);
}

extern "C" void kernel_launch(void* const* d_in, const int* in_sizes, int n_in,
                              void* d_out, int out_size)
{
    const float* h_in  = (const float*)d_in[1];
    const float* e     = (const float*)d_in[2];
    const float* Amat  = (const float*)d_in[3];
    const float* Wih   = (const float*)d_in[4];
    const float* Whh   = (const float*)d_in[5];
    const float* bih   = (const float*)d_in[6];
    const float* bhh   = (const float*)d_in[7];

    cudaFuncSetAttribute(tgemm_big<true >, cudaFuncAttributeMaxDynamicSharedMemorySize, BIG_SMEM_BYTES);
    cudaFuncSetAttribute(tgemm_big<false>, cudaFuncAttributeMaxDynamicSharedMemorySize, BIG_SMEM_BYTES);

    const float *r1W[4], *r1b[4], *r2W[4], *r2b[4];
    if (in_sizes[10] == 65536) {
        for (int i = 0; i < 4; i++) {
            r1W[i] = (const float*)d_in[8 + 4 * i];
            r1b[i] = (const float*)d_in[9 + 4 * i];
            r2W[i] = (const float*)d_in[10 + 4 * i];
            r2b[i] = (const float*)d_in[11 + 4 * i];
        }
    } else {
        for (int i = 0; i < 4; i++) {
            r1W[i] = (const float*)d_in[8 + 2 * i];
            r1b[i] = (const float*)d_in[9 + 2 * i];
            r2W[i] = (const float*)d_in[16 + 2 * i];
            r2b[i] = (const float*)d_in[17 + 2 * i];
        }
    }
    float* out = (float*)d_out;

    float *h_, *hproj, *m_, *gi, *gh, *mask, *t0, *t1, *gate, *val;
    cudaGetSymbolAddress((void**)&h_,    g_h);
    cudaGetSymbolAddress((void**)&hproj, g_hproj);
    cudaGetSymbolAddress((void**)&m_,    g_m);
    cudaGetSymbolAddress((void**)&gi,    g_gi);
    cudaGetSymbolAddress((void**)&gh,    g_gh);
    cudaGetSymbolAddress((void**)&mask,  g_mask);
    cudaGetSymbolAddress((void**)&t0,    g_t0);
    cudaGetSymbolAddress((void**)&t1,    g_t1);
    cudaGetSymbolAddress((void**)&gate,  g_gate);
    cudaGetSymbolAddress((void**)&val,   g_val);

    init_kernel<<<ROWS, 128>>>(h_in, h_, mask);

    for (int step = 0; step < 4; step++) {
        // hproj[b,l] = h[b] @ A[l]   (256 batched 128x512x512)
        gemm_big_l(h_, HH, Amat, MSGD, hproj, MSGD,
                   NN, MSGD, HH, nullptr, /*transb=*/false,
                   /*batches=*/BQ * LL, /*dv=*/LL,
                   (long long)NN * HH, 0,
                   0, (long long)HH * MSGD,
                   (long long)LL * NN * MSGD, (long long)NN * MSGD);

        agg_kernel<<<ROWS, 128>>>(e, hproj, m_);

        gemm_big_l(m_, MSGD, Wih, MSGD, gi, 3 * HH, ROWS, 3 * HH, MSGD, bih, true);
        gemm_big_l(h_, HH,   Whh, HH,   gh, 3 * HH, ROWS, 3 * HH, HH,   bhh, true);

        gru_kernel<<<ROWS, 128>>>(h_, gi, gh, mask);
    }

    // gate chain: relu(concat(h,h0) @ W0^T + b0) as two GEMMs (h0 tail = h_in pad)
    gemm_mlp_l(h_,   HH,  r1W[0],      2 * HH, t0, 128, ROWS, 128, HH,  nullptr, 0, false);
    gemm_mlp_l(h_in, FIN, r1W[0] + HH, 2 * HH, t0, 128, ROWS, 128, FIN, r1b[0],  1, true);
    gemm_mlp_l(t0, 128, r1W[1], 128, t1, 256, ROWS, 256, 128, r1b[1], 1, false);
    gemm_mlp_l(t1, 256, r1W[2], 256, t0, 128, ROWS, 128, 256, r1b[2], 1, false);
    gemm_mlp_l(t0, 128, r1W[3], 128, gate, TGT, ROWS, TGT, 128, r1b[3], 2, false);

    // val chain
    gemm_mlp_l(h_, HH,  r2W[0], HH,  t0, 128, ROWS, 128, HH,  r2b[0], 1, false);
    gemm_mlp_l(t0, 128, r2W[1], 128, t1, 256, ROWS, 256, 128, r2b[1], 1, false);
    gemm_mlp_l(t1, 256, r2W[2], 256, t0, 128, ROWS, 128, 256, r2b[2], 1, false);
    gemm_mlp_l(t0, 128, r2W[3], 128, val, TGT, ROWS, TGT, 128, r2b[3], 0, false);

    reduce_kernel<<<BQ, 128>>>(gate, val, mask, out);
}

// round 11
// speedup vs baseline: 1.7524x; 1.3873x over previous
#include <cuda_runtime.h>
#include <cuda_bf16.h>
#include <cstdint>

// Problem constants
#define BQ   64
#define NN   128
#define FIN  128
#define HH   512
#define MSGD 512
#define LL   4
#define ROWS (BQ*NN)      // 8192
#define TGT  12

// ---------------- scratch (device globals) ----------------
__device__ float g_h    [ROWS*HH];
__device__ float g_hproj[BQ*LL*NN*MSGD];
__device__ float g_m    [ROWS*MSGD];
__device__ float g_gi   [ROWS*3*HH];
__device__ float g_gh   [ROWS*3*HH];
__device__ float g_mask [ROWS];
__device__ float g_t0   [ROWS*256];
__device__ float g_t1   [ROWS*256];
__device__ float g_gate [ROWS*TGT];
__device__ float g_val  [ROWS*TGT];

// ---------------- bf16x3 helpers ----------------
__device__ __forceinline__ void bsplit1(float x, uint16_t& h, uint16_t& l) {
    __nv_bfloat16 b = __float2bfloat16_rn(x);
    h = __bfloat16_as_ushort(b);
    float r = x - __bfloat162float(b);
    l = __bfloat16_as_ushort(__float2bfloat16_rn(r));
}
__device__ __forceinline__ void bsplit4(float4 v, uint32_t& h0, uint32_t& h1,
                                        uint32_t& l0, uint32_t& l1) {
    uint16_t ha, hb, hc, hd, la, lb, lc, ld;
    bsplit1(v.x, ha, la);
    bsplit1(v.y, hb, lb);
    bsplit1(v.z, hc, lc);
    bsplit1(v.w, hd, ld);
    h0 = (uint32_t)ha | ((uint32_t)hb << 16);
    h1 = (uint32_t)hc | ((uint32_t)hd << 16);
    l0 = (uint32_t)la | ((uint32_t)lb << 16);
    l1 = (uint32_t)lc | ((uint32_t)ld << 16);
}
__device__ __forceinline__ void mma_bf16(float* d, const uint32_t* a, const uint32_t* b) {
    asm volatile(
        "mma.sync.aligned.m16n8k16.row.col.f32.bf16.bf16.f32 "
        "{%0,%1,%2,%3}, {%4,%5,%6,%7}, {%8,%9}, {%0,%1,%2,%3};\n"
        : "+f"(d[0]), "+f"(d[1]), "+f"(d[2]), "+f"(d[3])
        : "r"(a[0]), "r"(a[1]), "r"(a[2]), "r"(a[3]), "r"(b[0]), "r"(b[1]));
}
__device__ __forceinline__ void ldsm_x4(uint32_t& r0, uint32_t& r1, uint32_t& r2, uint32_t& r3,
                                        uint32_t addr) {
    asm volatile("ldmatrix.sync.aligned.m8n8.x4.shared.b16 {%0,%1,%2,%3}, [%4];"
                 : "=r"(r0), "=r"(r1), "=r"(r2), "=r"(r3) : "r"(addr));
}

#define ROWB 48            // bytes per smem row: 16 bf16 (32B) + 16B pad

// ================= BIG kernel: 128x128, BK=16, double-buffered, 2 CTAs/SM =================
#define APLANE (128 * ROWB)              // 6144 B
#define BUFB   (4 * APLANE)              // Ah,Al,Bh,Bl = 24576 B
#define BIG_SMEM_BYTES (2 * BUFB)        // 49152 B

template<bool TRANSB>
__global__ void __launch_bounds__(256, 2)
tgemm_big(const float* __restrict__ A, int lda,
          const float* __restrict__ Bm, int ldb,
          float* __restrict__ C, int ldc,
          int M, int N, int K,
          const float* __restrict__ bias,
          int dv,
          long long aHi, long long aLo,
          long long bHi, long long bLo,
          long long cHi, long long cLo)
{
    extern __shared__ char smc[];

    int z = blockIdx.z;
    int zh = z / dv, zl = z % dv;
    A  += zh*aHi + zl*aLo;
    Bm += zh*bHi + zl*bLo;
    C  += zh*cHi + zl*cLo;

    int tid  = threadIdx.x;
    int lane = tid & 31;
    int wid  = tid >> 5;
    int gid  = lane >> 2;
    int tig  = lane & 3;
    int quad = lane >> 3;
    int rowin= lane & 7;
    int wm   = (wid & 3) * 32;
    int wn   = (wid >> 2) * 64;
    int m0   = blockIdx.y * 128;
    int n0   = blockIdx.x * 128;

    uint32_t sbase = (uint32_t)__cvta_generic_to_shared(smc);

    // ldmatrix per-thread offsets (bytes, within plane)
    // A tiles: quad0=(mLow,kLow) quad1=(m+8,kLow) quad2=(mLow,k+8) quad3=(m+8,k+8)
    int aoff = ((quad & 1) * 8 + rowin) * ROWB + ((quad >> 1) * 16);
    // B tiles: quad0=(nLow,kLow) quad1=(nLow,k+8) quad2=(n+8,kLow) quad3=(n+8,k+8)
    int boff = ((quad >> 1) * 8 + rowin) * ROWB + ((quad & 1) * 16);

    float4 aS[2], bS[2];
    const float4 f4z = make_float4(0.f, 0.f, 0.f, 0.f);

    auto ldg = [&](int k0) {
#pragma unroll
        for (int i = 0; i < 2; i++) {
            int f = i * 256 + tid;
            int r = f >> 2;
            int kq = (f & 3) * 4;
            aS[i] = *(const float4*)(A + (size_t)(m0 + r) * lda + k0 + kq);
            if (TRANSB) {
                int n = n0 + r;
                bS[i] = (n < N) ? *(const float4*)(Bm + (size_t)n * ldb + k0 + kq) : f4z;
            } else {
                int rr = f >> 5;
                int c = (f & 31) * 4;
                int n = n0 + c;
                bS[i] = (n < N) ? *(const float4*)(Bm + (size_t)(k0 + rr) * ldb + n) : f4z;
            }
        }
    };
    auto sts = [&](int buf) {
        char* base = smc + buf * BUFB;
#pragma unroll
        for (int i = 0; i < 2; i++) {
            int f = i * 256 + tid;
            int r = f >> 2;
            int kq = (f & 3) * 4;
            uint32_t h0, h1, l0, l1;
            bsplit4(aS[i], h0, h1, l0, l1);
            *(uint2*)(base + r * ROWB + kq * 2)          = make_uint2(h0, h1);
            *(uint2*)(base + APLANE + r * ROWB + kq * 2) = make_uint2(l0, l1);
            if (TRANSB) {
                bsplit4(bS[i], h0, h1, l0, l1);
                *(uint2*)(base + 2*APLANE + r * ROWB + kq * 2) = make_uint2(h0, h1);
                *(uint2*)(base + 3*APLANE + r * ROWB + kq * 2) = make_uint2(l0, l1);
            } else {
                // transpose: global [k][n] -> smem [n][k]
                int rr = f >> 5;           // k
                int c = (f & 31) * 4;      // n
                float bv[4] = {bS[i].x, bS[i].y, bS[i].z, bS[i].w};
#pragma unroll
                for (int q = 0; q < 4; q++) {
                    uint16_t h, l;
                    bsplit1(bv[q], h, l);
                    *(uint16_t*)(base + 2*APLANE + (c + q) * ROWB + rr * 2) = h;
                    *(uint16_t*)(base + 3*APLANE + (c + q) * ROWB + rr * 2) = l;
                }
            }
        }
    };

    float acc[2][8][4];
#pragma unroll
    for (int mt = 0; mt < 2; mt++)
#pragma unroll
        for (int nt = 0; nt < 8; nt++)
#pragma unroll
            for (int q = 0; q < 4; q++) acc[mt][nt][q] = 0.f;

    ldg(0);
    sts(0);
    __syncthreads();

    int cur = 0;
    for (int k0 = 0; k0 < K; k0 += 16) {
        int nxt = k0 + 16;
        if (nxt < K) ldg(nxt);
        uint32_t bb  = sbase + cur * BUFB;
        uint32_t ahp = bb + wm * ROWB + aoff;
        uint32_t alp = ahp + APLANE;
        uint32_t bhp = bb + 2*APLANE + wn * ROWB + boff;
        uint32_t blp = bhp + APLANE;

        uint32_t afh[2][4], afl[2][4], bfh[8][2], bfl[8][2];
        ldsm_x4(afh[0][0], afh[0][1], afh[0][2], afh[0][3], ahp);
        ldsm_x4(afh[1][0], afh[1][1], afh[1][2], afh[1][3], ahp + 16 * ROWB);
        ldsm_x4(afl[0][0], afl[0][1], afl[0][2], afl[0][3], alp);
        ldsm_x4(afl[1][0], afl[1][1], afl[1][2], afl[1][3], alp + 16 * ROWB);
#pragma unroll
        for (int p = 0; p < 4; p++) {
            ldsm_x4(bfh[2*p][0], bfh[2*p][1], bfh[2*p+1][0], bfh[2*p+1][1], bhp + p * 16 * ROWB);
            ldsm_x4(bfl[2*p][0], bfl[2*p][1], bfl[2*p+1][0], bfl[2*p+1][1], blp + p * 16 * ROWB);
        }
#pragma unroll
        for (int mt = 0; mt < 2; mt++)
#pragma unroll
            for (int nt = 0; nt < 8; nt++) {
                mma_bf16(acc[mt][nt], afl[mt], bfh[nt]);
                mma_bf16(acc[mt][nt], afh[mt], bfl[nt]);
                mma_bf16(acc[mt][nt], afh[mt], bfh[nt]);
            }
        if (nxt < K) {
            sts(cur ^ 1);          // safe: buffer cur^1 reads finished at last sync
            __syncthreads();       // ONE barrier per tile
            cur ^= 1;
        }
    }

#pragma unroll
    for (int mt = 0; mt < 2; mt++) {
#pragma unroll
        for (int nt = 0; nt < 8; nt++) {
            int row = m0 + wm + mt * 16 + gid;
            int col = n0 + wn + nt * 8 + tig * 2;
            if (col < N) {
#pragma unroll
                for (int half = 0; half < 2; half++) {
                    int r = row + half * 8;
                    float v0 = acc[mt][nt][half * 2 + 0];
                    float v1 = acc[mt][nt][half * 2 + 1];
                    size_t idx = (size_t)r * ldc + col;
                    if (bias) {
                        v0 += __ldg(bias + col);
                        v1 += __ldg(bias + col + 1);
                    }
                    *(float2*)(C + idx) = make_float2(v0, v1);
                }
            }
        }
    }
}

// ================= MLP kernel: 128x64, static smem, 2 CTAs/SM =================
#define BPLANE_S (64 * ROWB)   // 3072 B

template<bool ACC>
__global__ void __launch_bounds__(256, 2)
tgemm_mlp(const float* __restrict__ A, int lda,
          const float* __restrict__ Bm, int ldb,
          float* __restrict__ C, int ldc,
          int M, int N, int K,
          const float* __restrict__ bias, int act)
{
    __shared__ __align__(16) char smc[2 * APLANE + 2 * BPLANE_S];  // 18432 B

    int tid  = threadIdx.x;
    int lane = tid & 31;
    int wid  = tid >> 5;
    int gid  = lane >> 2;
    int tig  = lane & 3;
    int quad = lane >> 3;
    int rowin= lane & 7;
    int wm   = (wid & 3) * 32;
    int wn   = (wid >> 2) * 32;
    int m0   = blockIdx.y * 128;
    int n0   = blockIdx.x * 64;

    uint32_t sbase = (uint32_t)__cvta_generic_to_shared(smc);
    int aoff = ((quad & 1) * 8 + rowin) * ROWB + ((quad >> 1) * 16);
    int boff = ((quad >> 1) * 8 + rowin) * ROWB + ((quad & 1) * 16);

    float4 aS[2], bS;
    const float4 f4z = make_float4(0.f, 0.f, 0.f, 0.f);

    auto ldg = [&](int k0) {
#pragma unroll
        for (int i = 0; i < 2; i++) {
            int f = i * 256 + tid;
            int r = f >> 2;
            int kq = (f & 3) * 4;
            aS[i] = *(const float4*)(A + (size_t)(m0 + r) * lda + k0 + kq);
        }
        int r = tid >> 2;
        int kq = (tid & 3) * 4;
        int n = n0 + r;
        bS = (n < N) ? *(const float4*)(Bm + (size_t)n * ldb + k0 + kq) : f4z;
    };
    auto sts = [&]() {
#pragma unroll
        for (int i = 0; i < 2; i++) {
            int f = i * 256 + tid;
            int r = f >> 2;
            int kq = (f & 3) * 4;
            uint32_t h0, h1, l0, l1;
            bsplit4(aS[i], h0, h1, l0, l1);
            *(uint2*)(smc + r * ROWB + kq * 2)          = make_uint2(h0, h1);
            *(uint2*)(smc + APLANE + r * ROWB + kq * 2) = make_uint2(l0, l1);
        }
        {
            int r = tid >> 2;
            int kq = (tid & 3) * 4;
            uint32_t h0, h1, l0, l1;
            bsplit4(bS, h0, h1, l0, l1);
            *(uint2*)(smc + 2*APLANE + r * ROWB + kq * 2)            = make_uint2(h0, h1);
            *(uint2*)(smc + 2*APLANE + BPLANE_S + r * ROWB + kq * 2) = make_uint2(l0, l1);
        }
    };

    float acc[2][4][4];
#pragma unroll
    for (int mt = 0; mt < 2; mt++)
#pragma unroll
        for (int nt = 0; nt < 4; nt++)
#pragma unroll
            for (int q = 0; q < 4; q++) acc[mt][nt][q] = 0.f;

    ldg(0);
    sts();
    __syncthreads();

    for (int k0 = 0; k0 < K; k0 += 16) {
        int nxt = k0 + 16;
        if (nxt < K) ldg(nxt);
        uint32_t ahp = sbase + wm * ROWB + aoff;
        uint32_t alp = ahp + APLANE;
        uint32_t bhp = sbase + 2*APLANE + wn * ROWB + boff;
        uint32_t blp = bhp + BPLANE_S;

        uint32_t afh[2][4], afl[2][4], bfh[4][2], bfl[4][2];
        ldsm_x4(afh[0][0], afh[0][1], afh[0][2], afh[0][3], ahp);
        ldsm_x4(afh[1][0], afh[1][1], afh[1][2], afh[1][3], ahp + 16 * ROWB);
        ldsm_x4(afl[0][0], afl[0][1], afl[0][2], afl[0][3], alp);
        ldsm_x4(afl[1][0], afl[1][1], afl[1][2], afl[1][3], alp + 16 * ROWB);
#pragma unroll
        for (int p = 0; p < 2; p++) {
            ldsm_x4(bfh[2*p][0], bfh[2*p][1], bfh[2*p+1][0], bfh[2*p+1][1], bhp + p * 16 * ROWB);
            ldsm_x4(bfl[2*p][0], bfl[2*p][1], bfl[2*p+1][0], bfl[2*p+1][1], blp + p * 16 * ROWB);
        }
#pragma unroll
        for (int mt = 0; mt < 2; mt++)
#pragma unroll
            for (int nt = 0; nt < 4; nt++) {
                mma_bf16(acc[mt][nt], afl[mt], bfh[nt]);
                mma_bf16(acc[mt][nt], afh[mt], bfl[nt]);
                mma_bf16(acc[mt][nt], afh[mt], bfh[nt]);
            }
        if (nxt < K) {
            __syncthreads();
            sts();
            __syncthreads();
        }
    }

#pragma unroll
    for (int mt = 0; mt < 2; mt++) {
#pragma unroll
        for (int nt = 0; nt < 4; nt++) {
            int row = m0 + wm + mt * 16 + gid;
            int col = n0 + wn + nt * 8 + tig * 2;
            if (col < N) {
#pragma unroll
                for (int half = 0; half < 2; half++) {
                    int r = row + half * 8;
                    float v0 = acc[mt][nt][half * 2 + 0];
                    float v1 = acc[mt][nt][half * 2 + 1];
                    size_t idx = (size_t)r * ldc + col;
                    if (ACC) {
                        float2 old = *(const float2*)(C + idx);
                        v0 += old.x; v1 += old.y;
                    }
                    if (bias) {
                        v0 += __ldg(bias + col);
                        v1 += __ldg(bias + col + 1);
                    }
                    if (act == 1) { v0 = fmaxf(v0, 0.f); v1 = fmaxf(v1, 0.f); }
                    else if (act == 2) {
                        v0 = 1.f / (1.f + __expf(-v0));
                        v1 = 1.f / (1.f + __expf(-v1));
                    }
                    *(float2*)(C + idx) = make_float2(v0, v1);
                }
            }
        }
    }
}

// ---------------- elementwise kernels ----------------
__global__ void init_kernel(const float* __restrict__ h_in,
                            float* __restrict__ h, float* __restrict__ mask)
{
    int row = blockIdx.x;
    int t = threadIdx.x;   // 128
    float v = h_in[(size_t)row * FIN + t];
    float s = fabsf(v);
#pragma unroll
    for (int o = 16; o; o >>= 1) s += __shfl_xor_sync(0xffffffffu, s, o);
    __shared__ float ws[4];
    if ((t & 31) == 0) ws[t >> 5] = s;
    __syncthreads();
    if (t == 0) {
        float tot = ws[0] + ws[1] + ws[2] + ws[3];
        mask[row] = (tot > 0.f) ? 1.f : 0.f;
    }
    float* hr = h + (size_t)row * HH;
    hr[t]         = v;
    hr[t + 128]   = 0.f;
    hr[t + 256]   = 0.f;
    hr[t + 384]   = 0.f;
}

__global__ void agg_kernel(const float* __restrict__ e,
                           const float* __restrict__ hproj,
                           float* __restrict__ m)
{
    int row = blockIdx.x;          // b*128 + v
    int b = row >> 7;
    int t = threadIdx.x;           // 128
    __shared__ int cnt;
    __shared__ int widx[NN];
    __shared__ int wlab[NN];
    if (t == 0) cnt = 0;
    __syncthreads();
    float ev = e[(size_t)row * NN + t];
    int lab = (int)(ev + 0.5f);
    if (lab >= 1) {
        int p = atomicAdd(&cnt, 1);
        widx[p] = t;
        wlab[p] = lab - 1;
    }
    __syncthreads();
    float a0 = 0.f, a1 = 0.f, a2 = 0.f, a3 = 0.f;
    int n = cnt;
    const float* hb = hproj + (size_t)b * LL * NN * MSGD;
    for (int i = 0; i < n; i++) {
        const float* src = hb + ((size_t)wlab[i] * NN + widx[i]) * MSGD;
        a0 += __ldg(src + t);
        a1 += __ldg(src + t + 128);
        a2 += __ldg(src + t + 256);
        a3 += __ldg(src + t + 384);
    }
    float* o = m + (size_t)row * MSGD;
    o[t]       = a0;
    o[t + 128] = a1;
    o[t + 256] = a2;
    o[t + 384] = a3;
}

__global__ void gru_kernel(float* __restrict__ h,
                           const float* __restrict__ gi,
                           const float* __restrict__ gh,
                           const float* __restrict__ mask)
{
    int row = blockIdx.x;
    int t = threadIdx.x;   // 128
    float mk = mask[row];
    const float* gir = gi + (size_t)row * 3 * HH;
    const float* ghr = gh + (size_t)row * 3 * HH;
    float* hr = h + (size_t)row * HH;
#pragma unroll
    for (int j = 0; j < 4; j++) {
        int idx = t + j * 128;
        float ir = gir[idx], iz = gir[idx + HH], in_ = gir[idx + 2 * HH];
        float hrv = ghr[idx], hz = ghr[idx + HH], hn = ghr[idx + 2 * HH];
        float r  = 1.f / (1.f + __expf(-(ir + hrv)));
        float z  = 1.f / (1.f + __expf(-(iz + hz)));
        float nn = tanhf(in_ + r * hn);
        float ho = hr[idx];
        hr[idx] = ((1.f - z) * nn + z * ho) * mk;
    }
}

__global__ void reduce_kernel(const float* __restrict__ gate,
                              const float* __restrict__ val,
                              const float* __restrict__ mask,
                              float* __restrict__ out)
{
    __shared__ float sm[TGT][NN];
    int b = blockIdx.x;
    int t = threadIdx.x;   // 128
    int row = b * NN + t;
    float mk = mask[row];
#pragma unroll
    for (int j = 0; j < TGT; j++)
        sm[j][t] = gate[(size_t)row * TGT + j] * val[(size_t)row * TGT + j] * mk;
    __syncthreads();
    for (int s = 64; s > 0; s >>= 1) {
        if (t < s) {
#pragma unroll
            for (int j = 0; j < TGT; j++) sm[j][t] += sm[j][t + s];
        }
        __syncthreads();
    }
    if (t < TGT) out[b * TGT + t] = sm[t][0];
}

// ---------------- host side ----------------
static void gemm_big_l(const float* A, int lda, const float* B, int ldb,
                       float* C, int ldc, int M, int N, int K,
                       const float* bias, bool transb,
                       int batches = 1, int dv = 1,
                       long long aHi = 0, long long aLo = 0,
                       long long bHi = 0, long long bLo = 0,
                       long long cHi = 0, long long cLo = 0)
{
    dim3 grid((N + 127) / 128, M / 128, batches);
    if (transb)
        tgemm_big<true ><<<grid, 256, BIG_SMEM_BYTES>>>(A, lda, B, ldb, C, ldc, M, N, K, bias, dv, aHi, aLo, bHi, bLo, cHi, cLo);
    else
        tgemm_big<false><<<grid, 256, BIG_SMEM_BYTES>>>(A, lda, B, ldb, C, ldc, M, N, K, bias, dv, aHi, aLo, bHi, bLo, cHi, cLo);
}

static void gemm_mlp_l(const float* A, int lda, const float* B, int ldb,
                       float* C, int ldc, int M, int N, int K,
                       const float* bias, int act, bool acc)
{
    dim3 grid((N + 63) / 64, M / 128, 1);
    if (acc) tgemm_mlp<true ><<<grid, 256>>>(A, lda, B, ldb, C, ldc, M, N, K, bias, act);
    else     tgemm_mlp<false><<<grid, 256>>>(A, lda, B, ldb, C, ldc, M, N, K, bias, act);
}

extern "C" void kernel_launch(void* const* d_in, const int* in_sizes, int n_in,
                              void* d_out, int out_size)
{
    const float* h_in  = (const float*)d_in[1];
    const float* e     = (const float*)d_in[2];
    const float* Amat  = (const float*)d_in[3];
    const float* Wih   = (const float*)d_in[4];
    const float* Whh   = (const float*)d_in[5];
    const float* bih   = (const float*)d_in[6];
    const float* bhh   = (const float*)d_in[7];

    cudaFuncSetAttribute(tgemm_big<true >, cudaFuncAttributeMaxDynamicSharedMemorySize, BIG_SMEM_BYTES);
    cudaFuncSetAttribute(tgemm_big<false>, cudaFuncAttributeMaxDynamicSharedMemorySize, BIG_SMEM_BYTES);

    const float *r1W[4], *r1b[4], *r2W[4], *r2b[4];
    if (in_sizes[10] == 65536) {
        for (int i = 0; i < 4; i++) {
            r1W[i] = (const float*)d_in[8 + 4 * i];
            r1b[i] = (const float*)d_in[9 + 4 * i];
            r2W[i] = (const float*)d_in[10 + 4 * i];
            r2b[i] = (const float*)d_in[11 + 4 * i];
        }
    } else {
        for (int i = 0; i < 4; i++) {
            r1W[i] = (const float*)d_in[8 + 2 * i];
            r1b[i] = (const float*)d_in[9 + 2 * i];
            r2W[i] = (const float*)d_in[16 + 2 * i];
            r2b[i] = (const float*)d_in[17 + 2 * i];
        }
    }
    float* out = (float*)d_out;

    float *h_, *hproj, *m_, *gi, *gh, *mask, *t0, *t1, *gate, *val;
    cudaGetSymbolAddress((void**)&h_,    g_h);
    cudaGetSymbolAddress((void**)&hproj, g_hproj);
    cudaGetSymbolAddress((void**)&m_,    g_m);
    cudaGetSymbolAddress((void**)&gi,    g_gi);
    cudaGetSymbolAddress((void**)&gh,    g_gh);
    cudaGetSymbolAddress((void**)&mask,  g_mask);
    cudaGetSymbolAddress((void**)&t0,    g_t0);
    cudaGetSymbolAddress((void**)&t1,    g_t1);
    cudaGetSymbolAddress((void**)&gate,  g_gate);
    cudaGetSymbolAddress((void**)&val,   g_val);

    init_kernel<<<ROWS, 128>>>(h_in, h_, mask);

    for (int step = 0; step < 4; step++) {
        // hproj[b,l] = h[b] @ A[l]   (256 batched 128x512x512)
        gemm_big_l(h_, HH, Amat, MSGD, hproj, MSGD,
                   NN, MSGD, HH, nullptr, /*transb=*/false,
                   /*batches=*/BQ * LL, /*dv=*/LL,
                   (long long)NN * HH, 0,
                   0, (long long)HH * MSGD,
                   (long long)LL * NN * MSGD, (long long)NN * MSGD);

        agg_kernel<<<ROWS, 128>>>(e, hproj, m_);

        gemm_big_l(m_, MSGD, Wih, MSGD, gi, 3 * HH, ROWS, 3 * HH, MSGD, bih, true);
        gemm_big_l(h_, HH,   Whh, HH,   gh, 3 * HH, ROWS, 3 * HH, HH,   bhh, true);

        gru_kernel<<<ROWS, 128>>>(h_, gi, gh, mask);
    }

    // gate chain: relu(concat(h,h0) @ W0^T + b0) as two GEMMs (h0 tail = h_in pad)
    gemm_mlp_l(h_,   HH,  r1W[0],      2 * HH, t0, 128, ROWS, 128, HH,  nullptr, 0, false);
    gemm_mlp_l(h_in, FIN, r1W[0] + HH, 2 * HH, t0, 128, ROWS, 128, FIN, r1b[0],  1, true);
    gemm_mlp_l(t0, 128, r1W[1], 128, t1, 256, ROWS, 256, 128, r1b[1], 1, false);
    gemm_mlp_l(t1, 256, r1W[2], 256, t0, 128, ROWS, 128, 256, r1b[2], 1, false);
    gemm_mlp_l(t0, 128, r1W[3], 128, gate, TGT, ROWS, TGT, 128, r1b[3], 2, false);

    // val chain
    gemm_mlp_l(h_, HH,  r2W[0], HH,  t0, 128, ROWS, 128, HH,  r2b[0], 1, false);
    gemm_mlp_l(t0, 128, r2W[1], 128, t1, 256, ROWS, 256, 128, r2b[1], 1, false);
    gemm_mlp_l(t1, 256, r2W[2], 256, t0, 128, ROWS, 128, 256, r2b[2], 1, false);
    gemm_mlp_l(t0, 128, r2W[3], 128, val, TGT, ROWS, TGT, 128, r2b[3], 0, false);

    reduce_kernel<<<BQ, 128>>>(gate, val, mask, out);
}